// round 3
// baseline (speedup 1.0000x reference)
#include <cuda_runtime.h>
#include <cstdint>

#define NN 100000
#define EE 1600000

// ---------------- scratch (device globals; no allocation allowed) ----------------
__device__ float g_B[128 * 256];                       // concatenated [Wl | Wr], K-major
__device__ float g_C[(size_t)NN * 256];                // GEMM out: [:,0:dout]=h@Wl, [:,dout:]=h@Wr
__device__ float g_agg[(size_t)NN * 128];              // scatter-add target
__device__ float g_h[(size_t)NN * 128];                // hidden activations
__device__ float g_inv[NN];                            // 1 / max(deg, 1)
__device__ float g_deg[NN];
__device__ int   g_src[EE];
__device__ int   g_dst[EE];
__device__ int   g_is64;

// ---------------- edge-index decode (dtype-robust) ----------------
__global__ void detect_kernel(const int* __restrict__ ei32) {
    if (threadIdx.x == 0 && blockIdx.x == 0) {
        int is64 = 1;
        for (int i = 0; i < 64; i++) {
            if (ei32[2 * i + 1] != 0) { is64 = 0; break; }
        }
        g_is64 = is64;
    }
}

__global__ void zero_deg_kernel(int n) {
    int i = blockIdx.x * blockDim.x + threadIdx.x;
    if (i < n) g_deg[i] = 0.0f;
}

// decode indices + accumulate degree in one pass
__global__ void convert_kernel(const void* __restrict__ ei, int E, int N) {
    int e = blockIdx.x * blockDim.x + threadIdx.x;
    if (e >= E) return;
    int s, d;
    if (g_is64) {
        const long long* p = (const long long*)ei;
        s = (int)p[e];
        d = (int)p[(size_t)E + e];
    } else {
        const int* p = (const int*)ei;
        s = p[e];
        d = p[E + e];
    }
    s = min(max(s, 0), N - 1);
    d = min(max(d, 0), N - 1);
    g_src[e] = s;
    g_dst[e] = d;
    atomicAdd(&g_deg[d], 1.0f);
}

__global__ void inv_kernel(int n) {
    int i = blockIdx.x * blockDim.x + threadIdx.x;
    if (i < n) g_inv[i] = 1.0f / fmaxf(g_deg[i], 1.0f);
}

__global__ void zero_agg_kernel(int count4) {  // count4 = number of float4s
    int i = blockIdx.x * blockDim.x + threadIdx.x;
    if (i < count4)
        reinterpret_cast<float4*>(g_agg)[i] = make_float4(0.f, 0.f, 0.f, 0.f);
}

__global__ void concat_kernel(const float* __restrict__ Wl, const float* __restrict__ Wr, int dout) {
    int W = 2 * dout;
    int id = blockIdx.x * blockDim.x + threadIdx.x;
    if (id < 128 * W) {
        int k = id / W, j = id % W;
        g_B[id] = (j < dout) ? Wl[k * dout + j] : Wr[k * dout + (j - dout)];
    }
}

// ---------------- GEMM: g_C[N,W] = A[N,128] @ g_B[128,W] ----------------
// 128x128 block tile, BK=8, 256 threads, 8x8 micro-tile.
template<int W, bool USE_H>
__global__ __launch_bounds__(256) void gemm_kernel(const float* __restrict__ Aext, int nrows) {
    __shared__ float As[8][128];   // As[k][m]
    __shared__ float Bs[8][128];   // Bs[k][n]

    const float* __restrict__ A = USE_H ? (const float*)g_h : Aext;

    const int bm = blockIdx.x * 128;
    const int bn = blockIdx.y * 128;
    const int t  = threadIdx.x;
    const int tx = t & 15;
    const int ty = t >> 4;

    const int am  = t >> 1;
    const int ak4 = (t & 1) * 4;
    const int bk  = t >> 5;
    const int bn4 = (t & 31) * 4;

    float acc[8][8];
#pragma unroll
    for (int i = 0; i < 8; i++)
#pragma unroll
        for (int j = 0; j < 8; j++) acc[i][j] = 0.f;

    const bool arow_ok = (bm + am) < nrows;
    const float* aptr = A + (size_t)(bm + am) * 128 + ak4;

    for (int kt = 0; kt < 128; kt += 8) {
        float4 a4 = make_float4(0.f, 0.f, 0.f, 0.f);
        if (arow_ok) a4 = *reinterpret_cast<const float4*>(aptr + kt);
        As[ak4 + 0][am] = a4.x;
        As[ak4 + 1][am] = a4.y;
        As[ak4 + 2][am] = a4.z;
        As[ak4 + 3][am] = a4.w;
        *reinterpret_cast<float4*>(&Bs[bk][bn4]) =
            *reinterpret_cast<const float4*>(&g_B[(kt + bk) * W + bn + bn4]);
        __syncthreads();

#pragma unroll
        for (int k = 0; k < 8; k++) {
            float ar[8], br[8];
            *reinterpret_cast<float4*>(ar)     = *reinterpret_cast<const float4*>(&As[k][ty * 4]);
            *reinterpret_cast<float4*>(ar + 4) = *reinterpret_cast<const float4*>(&As[k][64 + ty * 4]);
            *reinterpret_cast<float4*>(br)     = *reinterpret_cast<const float4*>(&Bs[k][tx * 4]);
            *reinterpret_cast<float4*>(br + 4) = *reinterpret_cast<const float4*>(&Bs[k][64 + tx * 4]);
#pragma unroll
            for (int i = 0; i < 8; i++)
#pragma unroll
                for (int j = 0; j < 8; j++)
                    acc[i][j] += ar[i] * br[j];
        }
        __syncthreads();
    }

#pragma unroll
    for (int ih = 0; ih < 2; ih++) {
#pragma unroll
        for (int i = 0; i < 4; i++) {
            int row = bm + ih * 64 + ty * 4 + i;
            if (row < nrows) {
                float* crow = g_C + (size_t)row * W + bn;
#pragma unroll
                for (int jh = 0; jh < 2; jh++) {
                    float4 v = make_float4(acc[ih * 4 + i][jh * 4 + 0],
                                           acc[ih * 4 + i][jh * 4 + 1],
                                           acc[ih * 4 + i][jh * 4 + 2],
                                           acc[ih * 4 + i][jh * 4 + 3]);
                    *reinterpret_cast<float4*>(crow + jh * 64 + tx * 4) = v;
                }
            }
        }
    }
}

// ---------------- scatter-add: g_agg[dst] += g_C[src, 0:DOUT] ----------------
template<int DOUT, int W>
__global__ __launch_bounds__(256) void scatter_kernel(int E) {
    constexpr int VPE = DOUT / 4;  // 32 or 16
    long long gid = (long long)blockIdx.x * blockDim.x + threadIdx.x;
    if (gid >= (long long)E * VPE) return;
    int e = (int)(gid / VPE);
    int v = (int)(gid % VPE);
    int src = g_src[e];
    int dst = g_dst[e];
    float4 val = *reinterpret_cast<const float4*>(&g_C[(size_t)src * W + v * 4]);
    float* p = &g_agg[(size_t)dst * DOUT + v * 4];
    atomicAdd(p + 0, val.x);
    atomicAdd(p + 1, val.y);
    atomicAdd(p + 2, val.z);
    atomicAdd(p + 3, val.w);
}

// ---------------- epilogue: out = agg*inv + bl + R  [+ BN + ReLU] ----------------
template<int DOUT, int W, bool DO_BN, bool TO_OUT>
__global__ __launch_bounds__(256) void epilogue_kernel(
    const float* __restrict__ bl,
    const float* __restrict__ bng, const float* __restrict__ bnb,
    const float* __restrict__ bnm, const float* __restrict__ bnv,
    float* __restrict__ out, int n) {
    constexpr int VPN = DOUT / 4;
    int gid = blockIdx.x * blockDim.x + threadIdx.x;
    if (gid >= n * VPN) return;
    int node = gid / VPN;
    int v = gid % VPN;
    float inv = g_inv[node];
    float4 a = *reinterpret_cast<const float4*>(&g_agg[(size_t)node * DOUT + v * 4]);
    float4 r = *reinterpret_cast<const float4*>(&g_C[(size_t)node * W + DOUT + v * 4]);
    float4 b = *reinterpret_cast<const float4*>(&bl[v * 4]);
    float o[4];
    o[0] = a.x * inv + b.x + r.x;
    o[1] = a.y * inv + b.y + r.y;
    o[2] = a.z * inv + b.z + r.z;
    o[3] = a.w * inv + b.w + r.w;
    if (DO_BN) {
        float4 gm = *reinterpret_cast<const float4*>(&bng[v * 4]);
        float4 bt = *reinterpret_cast<const float4*>(&bnb[v * 4]);
        float4 mm = *reinterpret_cast<const float4*>(&bnm[v * 4]);
        float4 vv = *reinterpret_cast<const float4*>(&bnv[v * 4]);
        o[0] = fmaxf((o[0] - mm.x) * (gm.x * rsqrtf(vv.x + 1e-5f)) + bt.x, 0.f);
        o[1] = fmaxf((o[1] - mm.y) * (gm.y * rsqrtf(vv.y + 1e-5f)) + bt.y, 0.f);
        o[2] = fmaxf((o[2] - mm.z) * (gm.z * rsqrtf(vv.z + 1e-5f)) + bt.z, 0.f);
        o[3] = fmaxf((o[3] - mm.w) * (gm.w * rsqrtf(vv.w + 1e-5f)) + bt.w, 0.f);
    }
    float4 ov = make_float4(o[0], o[1], o[2], o[3]);
    if (TO_OUT)
        *reinterpret_cast<float4*>(&out[(size_t)node * DOUT + v * 4]) = ov;
    else
        *reinterpret_cast<float4*>(&g_h[(size_t)node * DOUT + v * 4]) = ov;
}

// ---------------- launch ----------------
extern "C" void kernel_launch(void* const* d_in, const int* in_sizes, int n_in,
                              void* d_out, int out_size) {
    const float* x   = (const float*)d_in[0];
    const void*  ei  = d_in[1];
    const float* Wl0 = (const float*)d_in[2];
    const float* Wr0 = (const float*)d_in[3];
    const float* bl0 = (const float*)d_in[4];
    const float* Wl1 = (const float*)d_in[5];
    const float* Wr1 = (const float*)d_in[6];
    const float* bl1 = (const float*)d_in[7];
    const float* Wl2 = (const float*)d_in[8];
    const float* Wr2 = (const float*)d_in[9];
    const float* bl2 = (const float*)d_in[10];
    const float* g0 = (const float*)d_in[11];
    const float* b0 = (const float*)d_in[12];
    const float* m0 = (const float*)d_in[13];
    const float* v0 = (const float*)d_in[14];
    const float* g1 = (const float*)d_in[15];
    const float* b1 = (const float*)d_in[16];
    const float* m1 = (const float*)d_in[17];
    const float* v1 = (const float*)d_in[18];
    float* out = (float*)d_out;

    const int N = in_sizes[0] / 128;
    const int E = in_sizes[1] / 2;

    // decode edge index + degree + inverse (shared by all layers)
    detect_kernel<<<1, 32>>>((const int*)ei);
    zero_deg_kernel<<<(N + 255) / 256, 256>>>(N);
    convert_kernel<<<(E + 255) / 256, 256>>>(ei, E, N);
    inv_kernel<<<(N + 255) / 256, 256>>>(N);

    dim3 gemmGridWide((N + 127) / 128, 2);
    dim3 gemmGridNarrow((N + 127) / 128, 1);
    int scat128Blocks = (int)(((long long)E * 32 + 255) / 256);
    int scat64Blocks  = (int)(((long long)E * 16 + 255) / 256);
    int epi128Blocks  = (N * 32 + 255) / 256;
    int epi64Blocks   = (N * 16 + 255) / 256;
    int zero128Blocks = (N * 32 + 255) / 256;
    int zero64Blocks  = (N * 16 + 255) / 256;

    // ---- layer 0: x -> g_h (BN + ReLU) ----
    concat_kernel<<<(128 * 256 + 255) / 256, 256>>>(Wl0, Wr0, 128);
    gemm_kernel<256, false><<<gemmGridWide, 256>>>(x, N);
    zero_agg_kernel<<<zero128Blocks, 256>>>(N * 32);
    scatter_kernel<128, 256><<<scat128Blocks, 256>>>(E);
    epilogue_kernel<128, 256, true, false><<<epi128Blocks, 256>>>(bl0, g0, b0, m0, v0, nullptr, N);

    // ---- layer 1: g_h -> g_h (BN + ReLU) ----
    concat_kernel<<<(128 * 256 + 255) / 256, 256>>>(Wl1, Wr1, 128);
    gemm_kernel<256, true><<<gemmGridWide, 256>>>(nullptr, N);
    zero_agg_kernel<<<zero128Blocks, 256>>>(N * 32);
    scatter_kernel<128, 256><<<scat128Blocks, 256>>>(E);
    epilogue_kernel<128, 256, true, false><<<epi128Blocks, 256>>>(bl1, g1, b1, m1, v1, nullptr, N);

    // ---- layer 2: g_h -> out (no BN/ReLU) ----
    concat_kernel<<<(128 * 128 + 255) / 256, 256>>>(Wl2, Wr2, 64);
    gemm_kernel<128, true><<<gemmGridNarrow, 256>>>(nullptr, N);
    zero_agg_kernel<<<zero64Blocks, 256>>>(N * 16);
    scatter_kernel<64, 128><<<scat64Blocks, 256>>>(E);
    epilogue_kernel<64, 128, false, true><<<epi64Blocks, 256>>>(bl2, nullptr, nullptr, nullptr, nullptr, out, N);
}

// round 4
// speedup vs baseline: 2.1700x; 2.1700x over previous
#include <cuda_runtime.h>
#include <cstdint>

#define NN 100000
#define EE 1600000

// ---------------- scratch (device globals; no allocation allowed) ----------------
__device__ float g_B[128 * 256];                  // concatenated [Wl | Wr], K-major
__device__ float g_C[(size_t)NN * 256];           // GEMM out: [:,0:dout]=h@Wl, [:,dout:]=h@Wr
__device__ float g_h[(size_t)NN * 128];           // hidden activations
__device__ float g_inv[NN];                       // 1 / max(deg, 1)
__device__ int   g_degi[NN];
__device__ int   g_off[NN + 1];                   // CSR offsets (by dst)
__device__ int   g_cursor[NN];
__device__ int   g_csr[EE];                       // src ids grouped by dst
__device__ int   g_src[EE];
__device__ int   g_dst[EE];
__device__ int   g_is64;

// ---------------- edge-index decode (dtype-robust) ----------------
__global__ void detect_kernel(const int* __restrict__ ei32) {
    if (threadIdx.x == 0 && blockIdx.x == 0) {
        int is64 = 1;
        for (int i = 0; i < 64; i++) {
            if (ei32[2 * i + 1] != 0) { is64 = 0; break; }
        }
        g_is64 = is64;
    }
}

__global__ void zero_deg_kernel(int n) {
    int i = blockIdx.x * blockDim.x + threadIdx.x;
    if (i < n) g_degi[i] = 0;
}

// decode indices + accumulate integer degree in one pass
__global__ void convert_kernel(const void* __restrict__ ei, int E, int N) {
    int e = blockIdx.x * blockDim.x + threadIdx.x;
    if (e >= E) return;
    int s, d;
    if (g_is64) {
        const long long* p = (const long long*)ei;
        s = (int)p[e];
        d = (int)p[(size_t)E + e];
    } else {
        const int* p = (const int*)ei;
        s = p[e];
        d = p[E + e];
    }
    s = min(max(s, 0), N - 1);
    d = min(max(d, 0), N - 1);
    g_src[e] = s;
    g_dst[e] = d;
    atomicAdd(&g_degi[d], 1);
}

// single-block exclusive prefix sum over g_degi -> g_off; also fills g_inv, g_cursor
__global__ __launch_bounds__(1024) void scan_kernel(int n) {
    __shared__ int warp_sums[32];
    __shared__ int carry_s;
    if (threadIdx.x == 0) carry_s = 0;
    __syncthreads();
    const int lane = threadIdx.x & 31;
    const int wid  = threadIdx.x >> 5;
    for (int base = 0; base < n; base += 1024) {
        int i = base + (int)threadIdx.x;
        int v = (i < n) ? g_degi[i] : 0;
        // intra-warp inclusive scan
        int x = v;
#pragma unroll
        for (int o = 1; o < 32; o <<= 1) {
            int y = __shfl_up_sync(0xffffffffu, x, o);
            if (lane >= o) x += y;
        }
        if (lane == 31) warp_sums[wid] = x;
        __syncthreads();
        if (wid == 0) {
            int w = warp_sums[lane];
#pragma unroll
            for (int o = 1; o < 32; o <<= 1) {
                int y = __shfl_up_sync(0xffffffffu, w, o);
                if (lane >= o) w += y;
            }
            warp_sums[lane] = w;
        }
        __syncthreads();
        int incl = x + (wid > 0 ? warp_sums[wid - 1] : 0);
        int carry = carry_s;
        int total = warp_sums[31];
        if (i < n) {
            int excl = carry + incl - v;
            g_off[i] = excl;
            g_cursor[i] = excl;
            g_inv[i] = 1.0f / fmaxf((float)v, 1.0f);
        }
        __syncthreads();
        if (threadIdx.x == 0) carry_s = carry + total;
        __syncthreads();
    }
    if (threadIdx.x == 0) g_off[n] = carry_s;
}

__global__ void csr_fill_kernel(int E) {
    int e = blockIdx.x * blockDim.x + threadIdx.x;
    if (e >= E) return;
    int d = g_dst[e];
    int pos = atomicAdd(&g_cursor[d], 1);
    g_csr[pos] = g_src[e];
}

__global__ void concat_kernel(const float* __restrict__ Wl, const float* __restrict__ Wr, int dout) {
    int W = 2 * dout;
    int id = blockIdx.x * blockDim.x + threadIdx.x;
    if (id < 128 * W) {
        int k = id / W, j = id % W;
        g_B[id] = (j < dout) ? Wl[k * dout + j] : Wr[k * dout + (j - dout)];
    }
}

// ---------------- GEMM: g_C[N,W] = A[N,128] @ g_B[128,W] ----------------
// 128x128 block tile, BK=8, 256 threads, 8x8 micro-tile.
template<int W, bool USE_H>
__global__ __launch_bounds__(256) void gemm_kernel(const float* __restrict__ Aext, int nrows) {
    __shared__ float As[8][128];
    __shared__ float Bs[8][128];

    const float* __restrict__ A = USE_H ? (const float*)g_h : Aext;

    const int bm = blockIdx.x * 128;
    const int bn = blockIdx.y * 128;
    const int t  = threadIdx.x;
    const int tx = t & 15;
    const int ty = t >> 4;

    const int am  = t >> 1;
    const int ak4 = (t & 1) * 4;
    const int bk  = t >> 5;
    const int bn4 = (t & 31) * 4;

    float acc[8][8];
#pragma unroll
    for (int i = 0; i < 8; i++)
#pragma unroll
        for (int j = 0; j < 8; j++) acc[i][j] = 0.f;

    const bool arow_ok = (bm + am) < nrows;
    const float* aptr = A + (size_t)(bm + am) * 128 + ak4;

    for (int kt = 0; kt < 128; kt += 8) {
        float4 a4 = make_float4(0.f, 0.f, 0.f, 0.f);
        if (arow_ok) a4 = *reinterpret_cast<const float4*>(aptr + kt);
        As[ak4 + 0][am] = a4.x;
        As[ak4 + 1][am] = a4.y;
        As[ak4 + 2][am] = a4.z;
        As[ak4 + 3][am] = a4.w;
        *reinterpret_cast<float4*>(&Bs[bk][bn4]) =
            *reinterpret_cast<const float4*>(&g_B[(kt + bk) * W + bn + bn4]);
        __syncthreads();

#pragma unroll
        for (int k = 0; k < 8; k++) {
            float ar[8], br[8];
            *reinterpret_cast<float4*>(ar)     = *reinterpret_cast<const float4*>(&As[k][ty * 4]);
            *reinterpret_cast<float4*>(ar + 4) = *reinterpret_cast<const float4*>(&As[k][64 + ty * 4]);
            *reinterpret_cast<float4*>(br)     = *reinterpret_cast<const float4*>(&Bs[k][tx * 4]);
            *reinterpret_cast<float4*>(br + 4) = *reinterpret_cast<const float4*>(&Bs[k][64 + tx * 4]);
#pragma unroll
            for (int i = 0; i < 8; i++)
#pragma unroll
                for (int j = 0; j < 8; j++)
                    acc[i][j] += ar[i] * br[j];
        }
        __syncthreads();
    }

#pragma unroll
    for (int ih = 0; ih < 2; ih++) {
#pragma unroll
        for (int i = 0; i < 4; i++) {
            int row = bm + ih * 64 + ty * 4 + i;
            if (row < nrows) {
                float* crow = g_C + (size_t)row * W + bn;
#pragma unroll
                for (int jh = 0; jh < 2; jh++) {
                    float4 v = make_float4(acc[ih * 4 + i][jh * 4 + 0],
                                           acc[ih * 4 + i][jh * 4 + 1],
                                           acc[ih * 4 + i][jh * 4 + 2],
                                           acc[ih * 4 + i][jh * 4 + 3]);
                    *reinterpret_cast<float4*>(crow + jh * 64 + tx * 4) = v;
                }
            }
        }
    }
}

// ---------------- fused gather + epilogue: warp per dst node ----------------
// out[node] = (sum_{src in N(node)} g_C[src,0:DOUT]) * inv + bl + g_C[node,DOUT:2*DOUT]
//             [+ BN + ReLU]
template<int DOUT, int W, bool DO_BN, bool TO_OUT>
__global__ __launch_bounds__(256) void gather_kernel(
    const float* __restrict__ bl,
    const float* __restrict__ bng, const float* __restrict__ bnb,
    const float* __restrict__ bnm, const float* __restrict__ bnv,
    float* __restrict__ out, int n) {
    constexpr int F = DOUT / 32;  // floats per lane: 4 or 2
    int node = blockIdx.x * (blockDim.x >> 5) + (threadIdx.x >> 5);
    if (node >= n) return;
    int lane = threadIdx.x & 31;
    const int col = lane * F;

    float acc[F];
#pragma unroll
    for (int f = 0; f < F; f++) acc[f] = 0.f;

    int p = g_off[node];
    const int end = g_off[node + 1];

    // unroll by 2 for memory-level parallelism
    for (; p + 2 <= end; p += 2) {
        int s0 = g_csr[p];
        int s1 = g_csr[p + 1];
        if (F == 4) {
            float4 v0 = *reinterpret_cast<const float4*>(&g_C[(size_t)s0 * W + col]);
            float4 v1 = *reinterpret_cast<const float4*>(&g_C[(size_t)s1 * W + col]);
            acc[0] += v0.x + v1.x; acc[1] += v0.y + v1.y;
            acc[2] += v0.z + v1.z; acc[3] += v0.w + v1.w;
        } else {
            float2 v0 = *reinterpret_cast<const float2*>(&g_C[(size_t)s0 * W + col]);
            float2 v1 = *reinterpret_cast<const float2*>(&g_C[(size_t)s1 * W + col]);
            acc[0] += v0.x + v1.x; acc[1] += v0.y + v1.y;
        }
    }
    if (p < end) {
        int s0 = g_csr[p];
        if (F == 4) {
            float4 v0 = *reinterpret_cast<const float4*>(&g_C[(size_t)s0 * W + col]);
            acc[0] += v0.x; acc[1] += v0.y; acc[2] += v0.z; acc[3] += v0.w;
        } else {
            float2 v0 = *reinterpret_cast<const float2*>(&g_C[(size_t)s0 * W + col]);
            acc[0] += v0.x; acc[1] += v0.y;
        }
    }

    const float inv = g_inv[node];
    float o[F];
    const float* rrow = &g_C[(size_t)node * W + DOUT + col];
#pragma unroll
    for (int f = 0; f < F; f++)
        o[f] = acc[f] * inv + bl[col + f] + rrow[f];

    if (DO_BN) {
#pragma unroll
        for (int f = 0; f < F; f++) {
            float gm = bng[col + f], bt = bnb[col + f];
            float mm = bnm[col + f], vv = bnv[col + f];
            o[f] = fmaxf((o[f] - mm) * (gm * rsqrtf(vv + 1e-5f)) + bt, 0.f);
        }
    }

    float* wptr = TO_OUT ? &out[(size_t)node * DOUT + col]
                         : &g_h[(size_t)node * DOUT + col];
    if (F == 4)
        *reinterpret_cast<float4*>(wptr) = make_float4(o[0], o[1], o[2], o[3]);
    else
        *reinterpret_cast<float2*>(wptr) = make_float2(o[0], o[1]);
}

// ---------------- launch ----------------
extern "C" void kernel_launch(void* const* d_in, const int* in_sizes, int n_in,
                              void* d_out, int out_size) {
    const float* x   = (const float*)d_in[0];
    const void*  ei  = d_in[1];
    const float* Wl0 = (const float*)d_in[2];
    const float* Wr0 = (const float*)d_in[3];
    const float* bl0 = (const float*)d_in[4];
    const float* Wl1 = (const float*)d_in[5];
    const float* Wr1 = (const float*)d_in[6];
    const float* bl1 = (const float*)d_in[7];
    const float* Wl2 = (const float*)d_in[8];
    const float* Wr2 = (const float*)d_in[9];
    const float* bl2 = (const float*)d_in[10];
    const float* g0 = (const float*)d_in[11];
    const float* b0 = (const float*)d_in[12];
    const float* m0 = (const float*)d_in[13];
    const float* v0 = (const float*)d_in[14];
    const float* g1 = (const float*)d_in[15];
    const float* b1 = (const float*)d_in[16];
    const float* m1 = (const float*)d_in[17];
    const float* v1 = (const float*)d_in[18];
    float* out = (float*)d_out;

    const int N = in_sizes[0] / 128;
    const int E = in_sizes[1] / 2;

    // ---- CSR build (shared by all 3 layers) ----
    detect_kernel<<<1, 32>>>((const int*)ei);
    zero_deg_kernel<<<(N + 255) / 256, 256>>>(N);
    convert_kernel<<<(E + 255) / 256, 256>>>(ei, E, N);
    scan_kernel<<<1, 1024>>>(N);
    csr_fill_kernel<<<(E + 255) / 256, 256>>>(E);

    dim3 gemmGridWide((N + 127) / 128, 2);
    dim3 gemmGridNarrow((N + 127) / 128, 1);
    int gatherBlocks = (N + 7) / 8;  // 8 warps (256 threads) per block

    // ---- layer 0: x -> g_h (BN + ReLU) ----
    concat_kernel<<<(128 * 256 + 255) / 256, 256>>>(Wl0, Wr0, 128);
    gemm_kernel<256, false><<<gemmGridWide, 256>>>(x, N);
    gather_kernel<128, 256, true, false><<<gatherBlocks, 256>>>(bl0, g0, b0, m0, v0, nullptr, N);

    // ---- layer 1: g_h -> g_h (BN + ReLU) ----
    concat_kernel<<<(128 * 256 + 255) / 256, 256>>>(Wl1, Wr1, 128);
    gemm_kernel<256, true><<<gemmGridWide, 256>>>(nullptr, N);
    gather_kernel<128, 256, true, false><<<gatherBlocks, 256>>>(bl1, g1, b1, m1, v1, nullptr, N);

    // ---- layer 2: g_h -> out (no BN/ReLU) ----
    concat_kernel<<<(128 * 128 + 255) / 256, 256>>>(Wl2, Wr2, 64);
    gemm_kernel<128, true><<<gemmGridNarrow, 256>>>(nullptr, N);
    gather_kernel<64, 128, false, true><<<gatherBlocks, 256>>>(bl2, nullptr, nullptr, nullptr, nullptr, out, N);
}

// round 6
// speedup vs baseline: 3.5419x; 1.6322x over previous
#include <cuda_runtime.h>
#include <cstdint>

#define NN 100000
#define EE 1600000

// ---------------- scratch (device globals; no allocation allowed) ----------------
__device__ float g_B[128 * 256];                  // concatenated [Wl | Wr], K-major
__device__ float g_C[(size_t)NN * 256];           // GEMM out: [:,0:dout]=h@Wl, [:,dout:]=h@Wr
__device__ float g_h[(size_t)NN * 128];           // hidden activations
__device__ float g_inv[NN];                       // 1 / max(deg, 1)
__device__ int   g_degi[NN];
__device__ int   g_off[NN + 1];                   // CSR offsets (by dst)
__device__ int   g_cursor[NN];
__device__ int   g_csr[EE];                       // src ids grouped by dst
__device__ int   g_src[EE];
__device__ int   g_dst[EE];
__device__ int   g_bsum[256];                     // per-block scan sums
__device__ int   g_is64;

__device__ __forceinline__ uint32_t f2tf32(float f) {
    uint32_t r;
    asm("cvt.rna.tf32.f32 %0, %1;" : "=r"(r) : "f"(f));
    return r;
}

// ---------------- edge-index decode (dtype-robust) ----------------
__global__ void detect_kernel(const int* __restrict__ ei32) {
    if (threadIdx.x == 0 && blockIdx.x == 0) {
        int is64 = 1;
        for (int i = 0; i < 64; i++) {
            if (ei32[2 * i + 1] != 0) { is64 = 0; break; }
        }
        g_is64 = is64;
    }
}

__global__ void zero_deg_kernel(int n) {
    int i = blockIdx.x * blockDim.x + threadIdx.x;
    if (i < n) g_degi[i] = 0;
}

// decode indices + accumulate integer degree in one pass
__global__ void convert_kernel(const void* __restrict__ ei, int E, int N) {
    int e = blockIdx.x * blockDim.x + threadIdx.x;
    if (e >= E) return;
    int s, d;
    if (g_is64) {
        const long long* p = (const long long*)ei;
        s = (int)p[e];
        d = (int)p[(size_t)E + e];
    } else {
        const int* p = (const int*)ei;
        s = p[e];
        d = p[E + e];
    }
    s = min(max(s, 0), N - 1);
    d = min(max(d, 0), N - 1);
    g_src[e] = s;
    g_dst[e] = d;
    atomicAdd(&g_degi[d], 1);
}

// ---------------- parallel 3-phase exclusive scan ----------------
__global__ __launch_bounds__(1024) void scan_local_kernel(int n) {
    __shared__ int warp_sums[32];
    const int lane = threadIdx.x & 31;
    const int wid  = threadIdx.x >> 5;
    int i = blockIdx.x * 1024 + threadIdx.x;
    int v = (i < n) ? g_degi[i] : 0;
    int x = v;
#pragma unroll
    for (int o = 1; o < 32; o <<= 1) {
        int y = __shfl_up_sync(0xffffffffu, x, o);
        if (lane >= o) x += y;
    }
    if (lane == 31) warp_sums[wid] = x;
    __syncthreads();
    if (wid == 0) {
        int w = warp_sums[lane];
#pragma unroll
        for (int o = 1; o < 32; o <<= 1) {
            int y = __shfl_up_sync(0xffffffffu, w, o);
            if (lane >= o) w += y;
        }
        warp_sums[lane] = w;
    }
    __syncthreads();
    int incl = x + (wid > 0 ? warp_sums[wid - 1] : 0);
    if (i < n) g_off[i] = incl - v;  // block-local exclusive
    if (threadIdx.x == 1023) g_bsum[blockIdx.x] = incl;
}

__global__ void scan_bsums_kernel(int nb, int n) {
    if (threadIdx.x == 0 && blockIdx.x == 0) {
        int run = 0;
        for (int b = 0; b < nb; b++) {
            int t = g_bsum[b];
            g_bsum[b] = run;
            run += t;
        }
        g_off[n] = run;
    }
}

__global__ __launch_bounds__(1024) void scan_add_kernel(int n) {
    int i = blockIdx.x * 1024 + threadIdx.x;
    if (i >= n) return;
    int off = g_off[i] + g_bsum[blockIdx.x];
    g_off[i] = off;
    g_cursor[i] = off;
    g_inv[i] = 1.0f / fmaxf((float)g_degi[i], 1.0f);
}

__global__ void csr_fill_kernel(int E) {
    int e = blockIdx.x * blockDim.x + threadIdx.x;
    if (e >= E) return;
    int d = g_dst[e];
    int pos = atomicAdd(&g_cursor[d], 1);
    g_csr[pos] = g_src[e];
}

__global__ void concat_kernel(const float* __restrict__ Wl, const float* __restrict__ Wr, int dout) {
    int W = 2 * dout;
    int id = blockIdx.x * blockDim.x + threadIdx.x;
    if (id < 128 * W) {
        int k = id / W, j = id % W;
        g_B[id] = (j < dout) ? Wl[k * dout + j] : Wr[k * dout + (j - dout)];
    }
}

// ---------------- tf32 tensor-core GEMM: g_C[N,W] = A[N,128] @ g_B[128,W] ----------------
// 128x128 block tile, 8 warps, each warp 32(M)x64(N), mma.m16n8k8 tf32.
// smem: As[m][k] pad 36 (conflict-free frag loads), Bs[k][n] pad 132.
template<int W, bool USE_H>
__global__ __launch_bounds__(256) void gemm_tc_kernel(const float* __restrict__ Aext, int nrows) {
    __shared__ float As[128][36];
    __shared__ float Bs[32][132];

    const float* __restrict__ A = USE_H ? (const float*)g_h : Aext;

    const int bm = blockIdx.x * 128;
    const int bn = blockIdx.y * 128;
    const int t = threadIdx.x;
    const int lane = t & 31;
    const int wid = t >> 5;
    const int warpM = wid & 3;       // 0..3 -> M offset warpM*32
    const int warpN = wid >> 2;      // 0..1 -> N offset warpN*64
    const int g = lane >> 2;         // groupID 0..7
    const int tig = lane & 3;        // thread-in-group 0..3

    // global load mappings
    const int arow  = t >> 1;          // 0..127
    const int acol0 = (t & 1) * 16;    // 0 or 16
    const int bkk   = t >> 3;          // 0..31
    const int bn0   = (t & 7) * 4;     // 0,4,..,28

    float acc[2][8][4];
#pragma unroll
    for (int mt = 0; mt < 2; mt++)
#pragma unroll
        for (int nt = 0; nt < 8; nt++)
#pragma unroll
            for (int c = 0; c < 4; c++) acc[mt][nt][c] = 0.f;

    const bool arow_ok = (bm + arow) < nrows;
    const float* aptr = A + (size_t)(bm + arow) * 128;

    for (int kc = 0; kc < 128; kc += 32) {
        // stage A (convert to tf32 once here)
#pragma unroll
        for (int i = 0; i < 4; i++) {
            float4 v = make_float4(0.f, 0.f, 0.f, 0.f);
            if (arow_ok) v = *reinterpret_cast<const float4*>(aptr + kc + acol0 + i * 4);
            int c = acol0 + i * 4;
            *reinterpret_cast<float2*>(&As[arow][c]) =
                make_float2(__uint_as_float(f2tf32(v.x)), __uint_as_float(f2tf32(v.y)));
            *reinterpret_cast<float2*>(&As[arow][c + 2]) =
                make_float2(__uint_as_float(f2tf32(v.z)), __uint_as_float(f2tf32(v.w)));
        }
        // stage B
#pragma unroll
        for (int i = 0; i < 4; i++) {
            int nn = bn0 + i * 32;
            float4 v = *reinterpret_cast<const float4*>(&g_B[(size_t)(kc + bkk) * W + bn + nn]);
            *reinterpret_cast<float2*>(&Bs[bkk][nn]) =
                make_float2(__uint_as_float(f2tf32(v.x)), __uint_as_float(f2tf32(v.y)));
            *reinterpret_cast<float2*>(&Bs[bkk][nn + 2]) =
                make_float2(__uint_as_float(f2tf32(v.z)), __uint_as_float(f2tf32(v.w)));
        }
        __syncthreads();

#pragma unroll
        for (int ks = 0; ks < 4; ks++) {
            const int k8 = ks * 8;
            uint32_t a[2][4], b[8][2];
#pragma unroll
            for (int mt = 0; mt < 2; mt++) {
                int m0 = warpM * 32 + mt * 16 + g;
                a[mt][0] = __float_as_uint(As[m0][k8 + tig]);
                a[mt][1] = __float_as_uint(As[m0 + 8][k8 + tig]);
                a[mt][2] = __float_as_uint(As[m0][k8 + tig + 4]);
                a[mt][3] = __float_as_uint(As[m0 + 8][k8 + tig + 4]);
            }
#pragma unroll
            for (int nt = 0; nt < 8; nt++) {
                int n0 = warpN * 64 + nt * 8 + g;
                b[nt][0] = __float_as_uint(Bs[k8 + tig][n0]);
                b[nt][1] = __float_as_uint(Bs[k8 + tig + 4][n0]);
            }
#pragma unroll
            for (int mt = 0; mt < 2; mt++)
#pragma unroll
                for (int nt = 0; nt < 8; nt++) {
                    asm volatile(
                        "mma.sync.aligned.m16n8k8.row.col.f32.tf32.tf32.f32 "
                        "{%0,%1,%2,%3}, {%4,%5,%6,%7}, {%8,%9}, {%0,%1,%2,%3};"
                        : "+f"(acc[mt][nt][0]), "+f"(acc[mt][nt][1]),
                          "+f"(acc[mt][nt][2]), "+f"(acc[mt][nt][3])
                        : "r"(a[mt][0]), "r"(a[mt][1]), "r"(a[mt][2]), "r"(a[mt][3]),
                          "r"(b[nt][0]), "r"(b[nt][1]));
                }
        }
        __syncthreads();
    }

    // store C
#pragma unroll
    for (int mt = 0; mt < 2; mt++) {
        int mrow0 = bm + warpM * 32 + mt * 16 + g;
#pragma unroll
        for (int half = 0; half < 2; half++) {
            int row = mrow0 + half * 8;
            if (row < nrows) {
                float* crow = g_C + (size_t)row * W + bn + warpN * 64;
#pragma unroll
                for (int nt = 0; nt < 8; nt++) {
                    *reinterpret_cast<float2*>(&crow[nt * 8 + 2 * tig]) =
                        make_float2(acc[mt][nt][half * 2 + 0], acc[mt][nt][half * 2 + 1]);
                }
            }
        }
    }
}

// ---------------- fused gather + epilogue: warp per dst node ----------------
template<int DOUT, int W, bool DO_BN, bool TO_OUT>
__global__ __launch_bounds__(256) void gather_kernel(
    const float* __restrict__ bl,
    const float* __restrict__ bng, const float* __restrict__ bnb,
    const float* __restrict__ bnm, const float* __restrict__ bnv,
    float* __restrict__ out, int n) {
    constexpr int F = DOUT / 32;  // floats per lane: 4 or 2
    int node = blockIdx.x * (blockDim.x >> 5) + (threadIdx.x >> 5);
    if (node >= n) return;
    int lane = threadIdx.x & 31;
    const int col = lane * F;

    float acc[F];
#pragma unroll
    for (int f = 0; f < F; f++) acc[f] = 0.f;

    int p = g_off[node];
    const int end = g_off[node + 1];

    for (; p + 2 <= end; p += 2) {
        int s0 = g_csr[p];
        int s1 = g_csr[p + 1];
        if (F == 4) {
            float4 v0 = *reinterpret_cast<const float4*>(&g_C[(size_t)s0 * W + col]);
            float4 v1 = *reinterpret_cast<const float4*>(&g_C[(size_t)s1 * W + col]);
            acc[0] += v0.x + v1.x; acc[1] += v0.y + v1.y;
            acc[2] += v0.z + v1.z; acc[3] += v0.w + v1.w;
        } else {
            float2 v0 = *reinterpret_cast<const float2*>(&g_C[(size_t)s0 * W + col]);
            float2 v1 = *reinterpret_cast<const float2*>(&g_C[(size_t)s1 * W + col]);
            acc[0] += v0.x + v1.x; acc[1] += v0.y + v1.y;
        }
    }
    if (p < end) {
        int s0 = g_csr[p];
        if (F == 4) {
            float4 v0 = *reinterpret_cast<const float4*>(&g_C[(size_t)s0 * W + col]);
            acc[0] += v0.x; acc[1] += v0.y; acc[2] += v0.z; acc[3] += v0.w;
        } else {
            float2 v0 = *reinterpret_cast<const float2*>(&g_C[(size_t)s0 * W + col]);
            acc[0] += v0.x; acc[1] += v0.y;
        }
    }

    const float inv = g_inv[node];
    float o[F];
    const float* rrow = &g_C[(size_t)node * W + DOUT + col];
#pragma unroll
    for (int f = 0; f < F; f++)
        o[f] = acc[f] * inv + bl[col + f] + rrow[f];

    if (DO_BN) {
#pragma unroll
        for (int f = 0; f < F; f++) {
            float gm = bng[col + f], bt = bnb[col + f];
            float mm = bnm[col + f], vv = bnv[col + f];
            o[f] = fmaxf((o[f] - mm) * (gm * rsqrtf(vv + 1e-5f)) + bt, 0.f);
        }
    }

    float* wptr = TO_OUT ? &out[(size_t)node * DOUT + col]
                         : &g_h[(size_t)node * DOUT + col];
    if (F == 4)
        *reinterpret_cast<float4*>(wptr) = make_float4(o[0], o[1], o[2], o[3]);
    else
        *reinterpret_cast<float2*>(wptr) = make_float2(o[0], o[1]);
}

// ---------------- launch ----------------
extern "C" void kernel_launch(void* const* d_in, const int* in_sizes, int n_in,
                              void* d_out, int out_size) {
    const float* x   = (const float*)d_in[0];
    const void*  ei  = d_in[1];
    const float* Wl0 = (const float*)d_in[2];
    const float* Wr0 = (const float*)d_in[3];
    const float* bl0 = (const float*)d_in[4];
    const float* Wl1 = (const float*)d_in[5];
    const float* Wr1 = (const float*)d_in[6];
    const float* bl1 = (const float*)d_in[7];
    const float* Wl2 = (const float*)d_in[8];
    const float* Wr2 = (const float*)d_in[9];
    const float* bl2 = (const float*)d_in[10];
    const float* g0 = (const float*)d_in[11];
    const float* b0 = (const float*)d_in[12];
    const float* m0 = (const float*)d_in[13];
    const float* v0 = (const float*)d_in[14];
    const float* g1 = (const float*)d_in[15];
    const float* b1 = (const float*)d_in[16];
    const float* m1 = (const float*)d_in[17];
    const float* v1 = (const float*)d_in[18];
    float* out = (float*)d_out;

    const int N = in_sizes[0] / 128;
    const int E = in_sizes[1] / 2;
    const int nb = (N + 1023) / 1024;

    // ---- CSR build (shared by all 3 layers) ----
    detect_kernel<<<1, 32>>>((const int*)ei);
    zero_deg_kernel<<<(N + 255) / 256, 256>>>(N);
    convert_kernel<<<(E + 255) / 256, 256>>>(ei, E, N);
    scan_local_kernel<<<nb, 1024>>>(N);
    scan_bsums_kernel<<<1, 32>>>(nb, N);
    scan_add_kernel<<<nb, 1024>>>(N);
    csr_fill_kernel<<<(E + 255) / 256, 256>>>(E);

    dim3 gemmGridWide((N + 127) / 128, 2);
    dim3 gemmGridNarrow((N + 127) / 128, 1);
    int gatherBlocks = (N + 7) / 8;  // 8 warps per block

    // ---- layer 0: x -> g_h (BN + ReLU) ----
    concat_kernel<<<(128 * 256 + 255) / 256, 256>>>(Wl0, Wr0, 128);
    gemm_tc_kernel<256, false><<<gemmGridWide, 256>>>(x, N);
    gather_kernel<128, 256, true, false><<<gatherBlocks, 256>>>(bl0, g0, b0, m0, v0, nullptr, N);

    // ---- layer 1: g_h -> g_h (BN + ReLU) ----
    concat_kernel<<<(128 * 256 + 255) / 256, 256>>>(Wl1, Wr1, 128);
    gemm_tc_kernel<256, true><<<gemmGridWide, 256>>>(nullptr, N);
    gather_kernel<128, 256, true, false><<<gatherBlocks, 256>>>(bl1, g1, b1, m1, v1, nullptr, N);

    // ---- layer 2: g_h -> out (no BN/ReLU) ----
    concat_kernel<<<(128 * 128 + 255) / 256, 256>>>(Wl2, Wr2, 64);
    gemm_tc_kernel<128, true><<<gemmGridNarrow, 256>>>(nullptr, N);
    gather_kernel<64, 128, false, true><<<gatherBlocks, 256>>>(bl2, nullptr, nullptr, nullptr, nullptr, out, N);
}

// round 7
// speedup vs baseline: 3.9602x; 1.1181x over previous
#include <cuda_runtime.h>
#include <cuda_fp16.h>
#include <cstdint>

#define NN 100000
#define EE 1600000

// ---------------- scratch (device globals; no allocation allowed) ----------------
__device__ float  g_B[128 * 256];                  // concatenated [Wl | Wr], K-major
__device__ __half g_T[(size_t)NN * 128];           // GEMM out T-part (h@Wl), fp16
__device__ float  g_R[(size_t)NN * 128];           // GEMM out R-part (h@Wr), fp32
__device__ float  g_h[(size_t)NN * 128];           // hidden activations
__device__ float  g_inv[NN];                       // 1 / max(deg, 1)
__device__ int    g_degi[NN];
__device__ int    g_off[NN + 1];                   // CSR offsets (by dst)
__device__ int    g_cursor[NN];
__device__ int    g_csr[EE];                       // src ids grouped by dst
__device__ int    g_src[EE];
__device__ int    g_dst[EE];
__device__ int    g_bsum[256];                     // per-block scan sums
__device__ int    g_is64;

__device__ __forceinline__ uint32_t f2tf32(float f) {
    uint32_t r;
    asm("cvt.rna.tf32.f32 %0, %1;" : "=r"(r) : "f"(f));
    return r;
}

// ---------------- edge-index decode (dtype-robust) ----------------
__global__ void detect_kernel(const int* __restrict__ ei32) {
    if (threadIdx.x == 0 && blockIdx.x == 0) {
        int is64 = 1;
        for (int i = 0; i < 64; i++) {
            if (ei32[2 * i + 1] != 0) { is64 = 0; break; }
        }
        g_is64 = is64;
    }
}

__global__ void zero_deg_kernel(int n) {
    int i = blockIdx.x * blockDim.x + threadIdx.x;
    if (i < n) g_degi[i] = 0;
}

__global__ void convert_kernel(const void* __restrict__ ei, int E, int N) {
    int e = blockIdx.x * blockDim.x + threadIdx.x;
    if (e >= E) return;
    int s, d;
    if (g_is64) {
        const long long* p = (const long long*)ei;
        s = (int)p[e];
        d = (int)p[(size_t)E + e];
    } else {
        const int* p = (const int*)ei;
        s = p[e];
        d = p[E + e];
    }
    s = min(max(s, 0), N - 1);
    d = min(max(d, 0), N - 1);
    g_src[e] = s;
    g_dst[e] = d;
    atomicAdd(&g_degi[d], 1);
}

// ---------------- parallel 3-phase exclusive scan ----------------
__global__ __launch_bounds__(1024) void scan_local_kernel(int n) {
    __shared__ int warp_sums[32];
    const int lane = threadIdx.x & 31;
    const int wid  = threadIdx.x >> 5;
    int i = blockIdx.x * 1024 + threadIdx.x;
    int v = (i < n) ? g_degi[i] : 0;
    int x = v;
#pragma unroll
    for (int o = 1; o < 32; o <<= 1) {
        int y = __shfl_up_sync(0xffffffffu, x, o);
        if (lane >= o) x += y;
    }
    if (lane == 31) warp_sums[wid] = x;
    __syncthreads();
    if (wid == 0) {
        int w = warp_sums[lane];
#pragma unroll
        for (int o = 1; o < 32; o <<= 1) {
            int y = __shfl_up_sync(0xffffffffu, w, o);
            if (lane >= o) w += y;
        }
        warp_sums[lane] = w;
    }
    __syncthreads();
    int incl = x + (wid > 0 ? warp_sums[wid - 1] : 0);
    if (i < n) g_off[i] = incl - v;  // block-local exclusive
    if (threadIdx.x == 1023) g_bsum[blockIdx.x] = incl;
}

__global__ void scan_bsums_kernel(int nb, int n) {
    if (threadIdx.x == 0 && blockIdx.x == 0) {
        int run = 0;
        for (int b = 0; b < nb; b++) {
            int t = g_bsum[b];
            g_bsum[b] = run;
            run += t;
        }
        g_off[n] = run;
    }
}

__global__ __launch_bounds__(1024) void scan_add_kernel(int n) {
    int i = blockIdx.x * 1024 + threadIdx.x;
    if (i >= n) return;
    int off = g_off[i] + g_bsum[blockIdx.x];
    g_off[i] = off;
    g_cursor[i] = off;
    g_inv[i] = 1.0f / fmaxf((float)g_degi[i], 1.0f);
}

__global__ void csr_fill_kernel(int E) {
    int e = blockIdx.x * blockDim.x + threadIdx.x;
    if (e >= E) return;
    int d = g_dst[e];
    int pos = atomicAdd(&g_cursor[d], 1);
    g_csr[pos] = g_src[e];
}

__global__ void concat_kernel(const float* __restrict__ Wl, const float* __restrict__ Wr, int dout) {
    int W = 2 * dout;
    int id = blockIdx.x * blockDim.x + threadIdx.x;
    if (id < 128 * W) {
        int k = id / W, j = id % W;
        g_B[id] = (j < dout) ? Wl[k * dout + j] : Wr[k * dout + (j - dout)];
    }
}

// ---------------- tf32 tensor-core GEMM (software pipelined) ----------------
// C[N,W] = A[N,128] @ g_B[128,W]; T half of columns -> g_T (fp16), R half -> g_R (fp32).
// 128x128 block tile, 8 warps of 32(M)x64(N), mma.m16n8k8 tf32.
template<int W, bool USE_H>
__global__ __launch_bounds__(256) void gemm_tc_kernel(const float* __restrict__ Aext, int nrows) {
    constexpr int DOUT = W / 2;
    __shared__ float As[128][36];
    __shared__ float Bs[32][132];

    const float* __restrict__ A = USE_H ? (const float*)g_h : Aext;

    const int bm = blockIdx.x * 128;
    const int bn = blockIdx.y * 128;
    const int t = threadIdx.x;
    const int lane = t & 31;
    const int wid = t >> 5;
    const int warpM = wid & 3;
    const int warpN = wid >> 2;
    const int g = lane >> 2;
    const int tig = lane & 3;

    const int arow  = t >> 1;
    const int acol0 = (t & 1) * 16;
    const int bkk   = t >> 3;
    const int bn0   = (t & 7) * 4;

    float acc[2][8][4];
#pragma unroll
    for (int mt = 0; mt < 2; mt++)
#pragma unroll
        for (int nt = 0; nt < 8; nt++)
#pragma unroll
            for (int c = 0; c < 4; c++) acc[mt][nt][c] = 0.f;

    const bool arow_ok = (bm + arow) < nrows;
    const float* aptr = A + (size_t)(bm + arow) * 128;

    float4 aReg[4], bReg[4];

    // prologue: load chunk 0
#pragma unroll
    for (int i = 0; i < 4; i++) {
        aReg[i] = arow_ok ? *reinterpret_cast<const float4*>(aptr + acol0 + i * 4)
                          : make_float4(0.f, 0.f, 0.f, 0.f);
        bReg[i] = *reinterpret_cast<const float4*>(&g_B[(size_t)bkk * W + bn + bn0 + i * 32]);
    }

    for (int kc = 0; kc < 128; kc += 32) {
        // stage current regs -> smem (convert to tf32 once)
#pragma unroll
        for (int i = 0; i < 4; i++) {
            int c = acol0 + i * 4;
            *reinterpret_cast<float2*>(&As[arow][c]) =
                make_float2(__uint_as_float(f2tf32(aReg[i].x)), __uint_as_float(f2tf32(aReg[i].y)));
            *reinterpret_cast<float2*>(&As[arow][c + 2]) =
                make_float2(__uint_as_float(f2tf32(aReg[i].z)), __uint_as_float(f2tf32(aReg[i].w)));
            int nn = bn0 + i * 32;
            *reinterpret_cast<float2*>(&Bs[bkk][nn]) =
                make_float2(__uint_as_float(f2tf32(bReg[i].x)), __uint_as_float(f2tf32(bReg[i].y)));
            *reinterpret_cast<float2*>(&Bs[bkk][nn + 2]) =
                make_float2(__uint_as_float(f2tf32(bReg[i].z)), __uint_as_float(f2tf32(bReg[i].w)));
        }
        __syncthreads();

        // prefetch next chunk (overlaps with MMA below)
        if (kc + 32 < 128) {
#pragma unroll
            for (int i = 0; i < 4; i++) {
                aReg[i] = arow_ok ? *reinterpret_cast<const float4*>(aptr + kc + 32 + acol0 + i * 4)
                                  : make_float4(0.f, 0.f, 0.f, 0.f);
                bReg[i] = *reinterpret_cast<const float4*>(&g_B[(size_t)(kc + 32 + bkk) * W + bn + bn0 + i * 32]);
            }
        }

#pragma unroll
        for (int ks = 0; ks < 4; ks++) {
            const int k8 = ks * 8;
            uint32_t a[2][4], b[8][2];
#pragma unroll
            for (int mt = 0; mt < 2; mt++) {
                int m0 = warpM * 32 + mt * 16 + g;
                a[mt][0] = __float_as_uint(As[m0][k8 + tig]);
                a[mt][1] = __float_as_uint(As[m0 + 8][k8 + tig]);
                a[mt][2] = __float_as_uint(As[m0][k8 + tig + 4]);
                a[mt][3] = __float_as_uint(As[m0 + 8][k8 + tig + 4]);
            }
#pragma unroll
            for (int nt = 0; nt < 8; nt++) {
                int n0 = warpN * 64 + nt * 8 + g;
                b[nt][0] = __float_as_uint(Bs[k8 + tig][n0]);
                b[nt][1] = __float_as_uint(Bs[k8 + tig + 4][n0]);
            }
#pragma unroll
            for (int mt = 0; mt < 2; mt++)
#pragma unroll
                for (int nt = 0; nt < 8; nt++) {
                    asm volatile(
                        "mma.sync.aligned.m16n8k8.row.col.f32.tf32.tf32.f32 "
                        "{%0,%1,%2,%3}, {%4,%5,%6,%7}, {%8,%9}, {%0,%1,%2,%3};"
                        : "+f"(acc[mt][nt][0]), "+f"(acc[mt][nt][1]),
                          "+f"(acc[mt][nt][2]), "+f"(acc[mt][nt][3])
                        : "r"(a[mt][0]), "r"(a[mt][1]), "r"(a[mt][2]), "r"(a[mt][3]),
                          "r"(b[nt][0]), "r"(b[nt][1]));
                }
        }
        __syncthreads();
    }

    // store: T columns -> g_T (fp16), R columns -> g_R (fp32). 64-wide warp range
    // aligns with DOUT multiples, so the branch is warp-uniform.
    const int gn0 = bn + warpN * 64;
#pragma unroll
    for (int mt = 0; mt < 2; mt++) {
        int mrow0 = bm + warpM * 32 + mt * 16 + g;
#pragma unroll
        for (int hf = 0; hf < 2; hf++) {
            int row = mrow0 + hf * 8;
            if (row < nrows) {
                if (gn0 < DOUT) {
                    __half* trow = g_T + (size_t)row * DOUT + gn0;
#pragma unroll
                    for (int nt = 0; nt < 8; nt++) {
                        __half2 hv = __floats2half2_rn(acc[mt][nt][hf * 2 + 0],
                                                       acc[mt][nt][hf * 2 + 1]);
                        *reinterpret_cast<__half2*>(&trow[nt * 8 + 2 * tig]) = hv;
                    }
                } else {
                    float* rrow = g_R + (size_t)row * DOUT + (gn0 - DOUT);
#pragma unroll
                    for (int nt = 0; nt < 8; nt++) {
                        *reinterpret_cast<float2*>(&rrow[nt * 8 + 2 * tig]) =
                            make_float2(acc[mt][nt][hf * 2 + 0], acc[mt][nt][hf * 2 + 1]);
                    }
                }
            }
        }
    }
}

// ---------------- fused gather + epilogue: warp per dst node ----------------
// out[node] = (sum_{src} g_T[src]) * inv + bl + g_R[node]  [+ BN + ReLU]
template<int DOUT, bool DO_BN, bool TO_OUT>
__global__ __launch_bounds__(256) void gather_kernel(
    const float* __restrict__ bl,
    const float* __restrict__ bng, const float* __restrict__ bnb,
    const float* __restrict__ bnm, const float* __restrict__ bnv,
    float* __restrict__ out, int n) {
    constexpr int F = DOUT / 32;  // floats per lane: 4 or 2
    int node = blockIdx.x * (blockDim.x >> 5) + (threadIdx.x >> 5);
    if (node >= n) return;
    int lane = threadIdx.x & 31;
    const int col = lane * F;

    float acc[F];
#pragma unroll
    for (int f = 0; f < F; f++) acc[f] = 0.f;

    int p = g_off[node];
    const int end = g_off[node + 1];

    for (; p + 2 <= end; p += 2) {
        int s0 = g_csr[p];
        int s1 = g_csr[p + 1];
        if (F == 4) {
            uint2 r0 = *reinterpret_cast<const uint2*>(&g_T[(size_t)s0 * DOUT + col]);
            uint2 r1 = *reinterpret_cast<const uint2*>(&g_T[(size_t)s1 * DOUT + col]);
            float2 a0 = __half22float2(*reinterpret_cast<__half2*>(&r0.x));
            float2 a1 = __half22float2(*reinterpret_cast<__half2*>(&r0.y));
            float2 b0 = __half22float2(*reinterpret_cast<__half2*>(&r1.x));
            float2 b1 = __half22float2(*reinterpret_cast<__half2*>(&r1.y));
            acc[0] += a0.x + b0.x; acc[1] += a0.y + b0.y;
            acc[2] += a1.x + b1.x; acc[3] += a1.y + b1.y;
        } else {
            __half2 h0 = *reinterpret_cast<const __half2*>(&g_T[(size_t)s0 * DOUT + col]);
            __half2 h1 = *reinterpret_cast<const __half2*>(&g_T[(size_t)s1 * DOUT + col]);
            float2 a0 = __half22float2(h0);
            float2 b0 = __half22float2(h1);
            acc[0] += a0.x + b0.x; acc[1] += a0.y + b0.y;
        }
    }
    if (p < end) {
        int s0 = g_csr[p];
        if (F == 4) {
            uint2 r0 = *reinterpret_cast<const uint2*>(&g_T[(size_t)s0 * DOUT + col]);
            float2 a0 = __half22float2(*reinterpret_cast<__half2*>(&r0.x));
            float2 a1 = __half22float2(*reinterpret_cast<__half2*>(&r0.y));
            acc[0] += a0.x; acc[1] += a0.y; acc[2] += a1.x; acc[3] += a1.y;
        } else {
            __half2 h0 = *reinterpret_cast<const __half2*>(&g_T[(size_t)s0 * DOUT + col]);
            float2 a0 = __half22float2(h0);
            acc[0] += a0.x; acc[1] += a0.y;
        }
    }

    const float inv = g_inv[node];
    float o[F];
    const float* rrow = &g_R[(size_t)node * DOUT + col];
#pragma unroll
    for (int f = 0; f < F; f++)
        o[f] = acc[f] * inv + bl[col + f] + rrow[f];

    if (DO_BN) {
#pragma unroll
        for (int f = 0; f < F; f++) {
            float gm = bng[col + f], bt = bnb[col + f];
            float mm = bnm[col + f], vv = bnv[col + f];
            o[f] = fmaxf((o[f] - mm) * (gm * rsqrtf(vv + 1e-5f)) + bt, 0.f);
        }
    }

    float* wptr = TO_OUT ? &out[(size_t)node * DOUT + col]
                         : &g_h[(size_t)node * DOUT + col];
    if (F == 4)
        *reinterpret_cast<float4*>(wptr) = make_float4(o[0], o[1], o[2], o[3]);
    else
        *reinterpret_cast<float2*>(wptr) = make_float2(o[0], o[1]);
}

// ---------------- launch ----------------
extern "C" void kernel_launch(void* const* d_in, const int* in_sizes, int n_in,
                              void* d_out, int out_size) {
    const float* x   = (const float*)d_in[0];
    const void*  ei  = d_in[1];
    const float* Wl0 = (const float*)d_in[2];
    const float* Wr0 = (const float*)d_in[3];
    const float* bl0 = (const float*)d_in[4];
    const float* Wl1 = (const float*)d_in[5];
    const float* Wr1 = (const float*)d_in[6];
    const float* bl1 = (const float*)d_in[7];
    const float* Wl2 = (const float*)d_in[8];
    const float* Wr2 = (const float*)d_in[9];
    const float* bl2 = (const float*)d_in[10];
    const float* g0 = (const float*)d_in[11];
    const float* b0 = (const float*)d_in[12];
    const float* m0 = (const float*)d_in[13];
    const float* v0 = (const float*)d_in[14];
    const float* g1 = (const float*)d_in[15];
    const float* b1 = (const float*)d_in[16];
    const float* m1 = (const float*)d_in[17];
    const float* v1 = (const float*)d_in[18];
    float* out = (float*)d_out;

    const int N = in_sizes[0] / 128;
    const int E = in_sizes[1] / 2;
    const int nb = (N + 1023) / 1024;

    // ---- CSR build (shared by all 3 layers) ----
    detect_kernel<<<1, 32>>>((const int*)ei);
    zero_deg_kernel<<<(N + 255) / 256, 256>>>(N);
    convert_kernel<<<(E + 255) / 256, 256>>>(ei, E, N);
    scan_local_kernel<<<nb, 1024>>>(N);
    scan_bsums_kernel<<<1, 32>>>(nb, N);
    scan_add_kernel<<<nb, 1024>>>(N);
    csr_fill_kernel<<<(E + 255) / 256, 256>>>(E);

    dim3 gemmGridWide((N + 127) / 128, 2);
    dim3 gemmGridNarrow((N + 127) / 128, 1);
    int gatherBlocks = (N + 7) / 8;  // 8 warps per block

    // ---- layer 0: x -> g_h (BN + ReLU) ----
    concat_kernel<<<(128 * 256 + 255) / 256, 256>>>(Wl0, Wr0, 128);
    gemm_tc_kernel<256, false><<<gemmGridWide, 256>>>(x, N);
    gather_kernel<128, true, false><<<gatherBlocks, 256>>>(bl0, g0, b0, m0, v0, nullptr, N);

    // ---- layer 1: g_h -> g_h (BN + ReLU) ----
    concat_kernel<<<(128 * 256 + 255) / 256, 256>>>(Wl1, Wr1, 128);
    gemm_tc_kernel<256, true><<<gemmGridWide, 256>>>(nullptr, N);
    gather_kernel<128, true, false><<<gatherBlocks, 256>>>(bl1, g1, b1, m1, v1, nullptr, N);

    // ---- layer 2: g_h -> out (no BN/ReLU) ----
    concat_kernel<<<(128 * 128 + 255) / 256, 256>>>(Wl2, Wr2, 64);
    gemm_tc_kernel<128, true><<<gemmGridNarrow, 256>>>(nullptr, N);
    gather_kernel<64, false, true><<<gatherBlocks, 256>>>(bl2, nullptr, nullptr, nullptr, nullptr, out, N);
}

// round 9
// speedup vs baseline: 4.4322x; 1.1192x over previous
#include <cuda_runtime.h>
#include <cuda_fp16.h>
#include <cstdint>

#define NN 100000
#define EE 1600000

// ---------------- scratch (device globals; no allocation allowed) ----------------
__device__ __half g_Bh[256 * 128];                 // concatenated [Wl | Wr], N-major: g_Bh[j*128+k], fp16
__device__ __half g_T[(size_t)NN * 128];           // GEMM out T-part (h@Wl), fp16
__device__ float  g_R[(size_t)NN * 128];           // GEMM out R-part (h@Wr), fp32
__device__ float  g_h[(size_t)NN * 128];           // hidden activations
__device__ float  g_inv[NN];                       // 1 / max(deg, 1)
__device__ int    g_degi[NN];
__device__ int    g_off[NN + 1];                   // CSR offsets (by dst)
__device__ int    g_cursor[NN];
__device__ int    g_csr[EE];                       // src ids grouped by dst
__device__ int    g_src[EE];
__device__ int    g_dst[EE];
__device__ int    g_bsum[256];                     // per-block scan sums
__device__ int    g_is64;

__device__ __forceinline__ uint32_t h2_to_u32(__half2 h) {
    return *reinterpret_cast<uint32_t*>(&h);
}

// ---------------- edge-index decode (dtype-robust) ----------------
__global__ void detect_kernel(const int* __restrict__ ei32) {
    if (threadIdx.x == 0 && blockIdx.x == 0) {
        int is64 = 1;
        for (int i = 0; i < 64; i++) {
            if (ei32[2 * i + 1] != 0) { is64 = 0; break; }
        }
        g_is64 = is64;
    }
}

__global__ void zero_deg_kernel(int n) {
    int i = blockIdx.x * blockDim.x + threadIdx.x;
    if (i < n) g_degi[i] = 0;
}

__global__ void convert_kernel(const void* __restrict__ ei, int E, int N) {
    int e = blockIdx.x * blockDim.x + threadIdx.x;
    if (e >= E) return;
    int s, d;
    if (g_is64) {
        const long long* p = (const long long*)ei;
        s = (int)p[e];
        d = (int)p[(size_t)E + e];
    } else {
        const int* p = (const int*)ei;
        s = p[e];
        d = p[E + e];
    }
    s = min(max(s, 0), N - 1);
    d = min(max(d, 0), N - 1);
    g_src[e] = s;
    g_dst[e] = d;
    atomicAdd(&g_degi[d], 1);
}

// ---------------- parallel 3-phase exclusive scan ----------------
__global__ __launch_bounds__(1024) void scan_local_kernel(int n) {
    __shared__ int warp_sums[32];
    const int lane = threadIdx.x & 31;
    const int wid  = threadIdx.x >> 5;
    int i = blockIdx.x * 1024 + threadIdx.x;
    int v = (i < n) ? g_degi[i] : 0;
    int x = v;
#pragma unroll
    for (int o = 1; o < 32; o <<= 1) {
        int y = __shfl_up_sync(0xffffffffu, x, o);
        if (lane >= o) x += y;
    }
    if (lane == 31) warp_sums[wid] = x;
    __syncthreads();
    if (wid == 0) {
        int w = warp_sums[lane];
#pragma unroll
        for (int o = 1; o < 32; o <<= 1) {
            int y = __shfl_up_sync(0xffffffffu, w, o);
            if (lane >= o) w += y;
        }
        warp_sums[lane] = w;
    }
    __syncthreads();
    int incl = x + (wid > 0 ? warp_sums[wid - 1] : 0);
    if (i < n) g_off[i] = incl - v;  // block-local exclusive
    if (threadIdx.x == 1023) g_bsum[blockIdx.x] = incl;
}

__global__ void scan_bsums_kernel(int nb, int n) {
    if (threadIdx.x == 0 && blockIdx.x == 0) {
        int run = 0;
        for (int b = 0; b < nb; b++) {
            int t = g_bsum[b];
            g_bsum[b] = run;
            run += t;
        }
        g_off[n] = run;
    }
}

__global__ __launch_bounds__(1024) void scan_add_kernel(int n) {
    int i = blockIdx.x * 1024 + threadIdx.x;
    if (i >= n) return;
    int off = g_off[i] + g_bsum[blockIdx.x];
    g_off[i] = off;
    g_cursor[i] = off;
    g_inv[i] = 1.0f / fmaxf((float)g_degi[i], 1.0f);
}

__global__ void csr_fill_kernel(int E) {
    int e = blockIdx.x * blockDim.x + threadIdx.x;
    if (e >= E) return;
    int d = g_dst[e];
    int pos = atomicAdd(&g_cursor[d], 1);
    g_csr[pos] = g_src[e];
}

// weights -> fp16, N-major layout g_Bh[j][k]
__global__ void concat_kernel(const float* __restrict__ Wl, const float* __restrict__ Wr, int dout) {
    int W = 2 * dout;
    int id = blockIdx.x * blockDim.x + threadIdx.x;
    if (id < W * 128) {
        int j = id >> 7, k = id & 127;
        float v = (j < dout) ? Wl[k * dout + j] : Wr[k * dout + (j - dout)];
        g_Bh[id] = __float2half_rn(v);
    }
}

// ---------------- fp16 tensor-core GEMM (software pipelined) ----------------
// C[N,W] = A[N,128] @ B[128,W]; T half of columns -> g_T (fp16), R half -> g_R (fp32).
// 128x128 block tile, 8 warps of 32(M)x64(N), mma.m16n8k16 f16.f16.f32.
// smem: As[m][40] half, Bs[n][40] half (k-contiguous, conflict-free fragments).
template<int W, bool USE_H>
__global__ __launch_bounds__(256) void gemm_tc_kernel(const float* __restrict__ Aext, int nrows) {
    constexpr int DOUT = W / 2;
    __shared__ __half As[128][40];
    __shared__ __half Bs[128][40];

    const float* __restrict__ A = USE_H ? (const float*)g_h : Aext;

    const int bm = blockIdx.x * 128;
    const int bn = blockIdx.y * 128;
    const int t = threadIdx.x;
    const int lane = t & 31;
    const int wid = t >> 5;
    const int warpM = wid & 3;
    const int warpN = wid >> 2;
    const int g = lane >> 2;
    const int tig = lane & 3;

    // staging mappings: row = t>>1 (0..127), k-half = (t&1)*16
    const int srow = t >> 1;
    const int skoff = (t & 1) * 16;

    float acc[2][8][4];
#pragma unroll
    for (int mt = 0; mt < 2; mt++)
#pragma unroll
        for (int nt = 0; nt < 8; nt++)
#pragma unroll
            for (int c = 0; c < 4; c++) acc[mt][nt][c] = 0.f;

    const bool arow_ok = (bm + srow) < nrows;
    const float* aptr = A + (size_t)(bm + srow) * 128 + skoff;
    const __half* bptr = g_Bh + (size_t)(bn + srow) * 128 + skoff;

    float4 aReg[4];
    uint4  bReg[2];

    // prologue: load chunk 0 (k = 0..31, this thread's 16-k slice)
#pragma unroll
    for (int i = 0; i < 4; i++)
        aReg[i] = arow_ok ? *reinterpret_cast<const float4*>(aptr + i * 4)
                          : make_float4(0.f, 0.f, 0.f, 0.f);
    bReg[0] = *reinterpret_cast<const uint4*>(bptr);
    bReg[1] = *reinterpret_cast<const uint4*>(bptr + 8);

    for (int kc = 0; kc < 128; kc += 32) {
        // stage regs -> smem (A: fp32->fp16 convert; B: direct copy)
        {
            uint4 u0, u1;
            u0.x = h2_to_u32(__floats2half2_rn(aReg[0].x, aReg[0].y));
            u0.y = h2_to_u32(__floats2half2_rn(aReg[0].z, aReg[0].w));
            u0.z = h2_to_u32(__floats2half2_rn(aReg[1].x, aReg[1].y));
            u0.w = h2_to_u32(__floats2half2_rn(aReg[1].z, aReg[1].w));
            u1.x = h2_to_u32(__floats2half2_rn(aReg[2].x, aReg[2].y));
            u1.y = h2_to_u32(__floats2half2_rn(aReg[2].z, aReg[2].w));
            u1.z = h2_to_u32(__floats2half2_rn(aReg[3].x, aReg[3].y));
            u1.w = h2_to_u32(__floats2half2_rn(aReg[3].z, aReg[3].w));
            *reinterpret_cast<uint4*>(&As[srow][skoff])     = u0;
            *reinterpret_cast<uint4*>(&As[srow][skoff + 8]) = u1;
            *reinterpret_cast<uint4*>(&Bs[srow][skoff])     = bReg[0];
            *reinterpret_cast<uint4*>(&Bs[srow][skoff + 8]) = bReg[1];
        }
        __syncthreads();

        // prefetch next chunk (overlaps with MMA below)
        if (kc + 32 < 128) {
#pragma unroll
            for (int i = 0; i < 4; i++)
                aReg[i] = arow_ok ? *reinterpret_cast<const float4*>(aptr + kc + 32 + i * 4)
                                  : make_float4(0.f, 0.f, 0.f, 0.f);
            bReg[0] = *reinterpret_cast<const uint4*>(bptr + kc + 32);
            bReg[1] = *reinterpret_cast<const uint4*>(bptr + kc + 32 + 8);
        }

#pragma unroll
        for (int ks = 0; ks < 2; ks++) {
            const int kk = ks * 16;
            uint32_t a[2][4], b[8][2];
#pragma unroll
            for (int mt = 0; mt < 2; mt++) {
                int m0 = warpM * 32 + mt * 16 + g;
                a[mt][0] = *reinterpret_cast<const uint32_t*>(&As[m0][kk + 2 * tig]);
                a[mt][1] = *reinterpret_cast<const uint32_t*>(&As[m0 + 8][kk + 2 * tig]);
                a[mt][2] = *reinterpret_cast<const uint32_t*>(&As[m0][kk + 2 * tig + 8]);
                a[mt][3] = *reinterpret_cast<const uint32_t*>(&As[m0 + 8][kk + 2 * tig + 8]);
            }
#pragma unroll
            for (int nt = 0; nt < 8; nt++) {
                int n0 = warpN * 64 + nt * 8 + g;
                b[nt][0] = *reinterpret_cast<const uint32_t*>(&Bs[n0][kk + 2 * tig]);
                b[nt][1] = *reinterpret_cast<const uint32_t*>(&Bs[n0][kk + 2 * tig + 8]);
            }
#pragma unroll
            for (int mt = 0; mt < 2; mt++)
#pragma unroll
                for (int nt = 0; nt < 8; nt++) {
                    asm volatile(
                        "mma.sync.aligned.m16n8k16.row.col.f32.f16.f16.f32 "
                        "{%0,%1,%2,%3}, {%4,%5,%6,%7}, {%8,%9}, {%0,%1,%2,%3};"
                        : "+f"(acc[mt][nt][0]), "+f"(acc[mt][nt][1]),
                          "+f"(acc[mt][nt][2]), "+f"(acc[mt][nt][3])
                        : "r"(a[mt][0]), "r"(a[mt][1]), "r"(a[mt][2]), "r"(a[mt][3]),
                          "r"(b[nt][0]), "r"(b[nt][1]));
                }
        }
        __syncthreads();
    }

    // store: T columns -> g_T (fp16), R columns -> g_R (fp32). 64-wide warp range
    // aligns with DOUT multiples, so the branch is warp-uniform.
    const int gn0 = bn + warpN * 64;
#pragma unroll
    for (int mt = 0; mt < 2; mt++) {
        int mrow0 = bm + warpM * 32 + mt * 16 + g;
#pragma unroll
        for (int hf = 0; hf < 2; hf++) {
            int row = mrow0 + hf * 8;
            if (row < nrows) {
                if (gn0 < DOUT) {
                    __half* trow = g_T + (size_t)row * DOUT + gn0;
#pragma unroll
                    for (int nt = 0; nt < 8; nt++) {
                        __half2 hv = __floats2half2_rn(acc[mt][nt][hf * 2 + 0],
                                                       acc[mt][nt][hf * 2 + 1]);
                        *reinterpret_cast<__half2*>(&trow[nt * 8 + 2 * tig]) = hv;
                    }
                } else {
                    float* rrow = g_R + (size_t)row * DOUT + (gn0 - DOUT);
#pragma unroll
                    for (int nt = 0; nt < 8; nt++) {
                        *reinterpret_cast<float2*>(&rrow[nt * 8 + 2 * tig]) =
                            make_float2(acc[mt][nt][hf * 2 + 0], acc[mt][nt][hf * 2 + 1]);
                    }
                }
            }
        }
    }
}

// ---------------- fused gather + epilogue: warp per dst node ----------------
// out[node] = (sum_{src} g_T[src]) * inv + bl + g_R[node]  [+ BN + ReLU]
template<int DOUT, bool DO_BN, bool TO_OUT>
__global__ __launch_bounds__(256) void gather_kernel(
    const float* __restrict__ bl,
    const float* __restrict__ bng, const float* __restrict__ bnb,
    const float* __restrict__ bnm, const float* __restrict__ bnv,
    float* __restrict__ out, int n) {
    constexpr int F = DOUT / 32;  // floats per lane: 4 or 2
    int node = blockIdx.x * (blockDim.x >> 5) + (threadIdx.x >> 5);
    if (node >= n) return;
    int lane = threadIdx.x & 31;
    const int col = lane * F;

    float acc[F];
#pragma unroll
    for (int f = 0; f < F; f++) acc[f] = 0.f;

    int p = g_off[node];
    const int end = g_off[node + 1];

    // unroll by 4 for memory-level parallelism
    for (; p + 4 <= end; p += 4) {
        int s0 = g_csr[p], s1 = g_csr[p + 1], s2 = g_csr[p + 2], s3 = g_csr[p + 3];
        if (F == 4) {
            uint2 r0 = *reinterpret_cast<const uint2*>(&g_T[(size_t)s0 * DOUT + col]);
            uint2 r1 = *reinterpret_cast<const uint2*>(&g_T[(size_t)s1 * DOUT + col]);
            uint2 r2 = *reinterpret_cast<const uint2*>(&g_T[(size_t)s2 * DOUT + col]);
            uint2 r3 = *reinterpret_cast<const uint2*>(&g_T[(size_t)s3 * DOUT + col]);
#pragma unroll
            for (int q = 0; q < 4; q++) {
                uint2 r = (q == 0) ? r0 : (q == 1) ? r1 : (q == 2) ? r2 : r3;
                float2 a0 = __half22float2(*reinterpret_cast<__half2*>(&r.x));
                float2 a1 = __half22float2(*reinterpret_cast<__half2*>(&r.y));
                acc[0] += a0.x; acc[1] += a0.y; acc[2] += a1.x; acc[3] += a1.y;
            }
        } else {
            __half2 h0 = *reinterpret_cast<const __half2*>(&g_T[(size_t)s0 * DOUT + col]);
            __half2 h1 = *reinterpret_cast<const __half2*>(&g_T[(size_t)s1 * DOUT + col]);
            __half2 h2 = *reinterpret_cast<const __half2*>(&g_T[(size_t)s2 * DOUT + col]);
            __half2 h3 = *reinterpret_cast<const __half2*>(&g_T[(size_t)s3 * DOUT + col]);
            float2 a0 = __half22float2(h0), a1 = __half22float2(h1);
            float2 a2 = __half22float2(h2), a3 = __half22float2(h3);
            acc[0] += a0.x + a1.x + a2.x + a3.x;
            acc[1] += a0.y + a1.y + a2.y + a3.y;
        }
    }
    for (; p < end; p++) {
        int s0 = g_csr[p];
        if (F == 4) {
            uint2 r0 = *reinterpret_cast<const uint2*>(&g_T[(size_t)s0 * DOUT + col]);
            float2 a0 = __half22float2(*reinterpret_cast<__half2*>(&r0.x));
            float2 a1 = __half22float2(*reinterpret_cast<__half2*>(&r0.y));
            acc[0] += a0.x; acc[1] += a0.y; acc[2] += a1.x; acc[3] += a1.y;
        } else {
            __half2 h0 = *reinterpret_cast<const __half2*>(&g_T[(size_t)s0 * DOUT + col]);
            float2 a0 = __half22float2(h0);
            acc[0] += a0.x; acc[1] += a0.y;
        }
    }

    const float inv = g_inv[node];
    float o[F];
    const float* rrow = &g_R[(size_t)node * DOUT + col];
#pragma unroll
    for (int f = 0; f < F; f++)
        o[f] = acc[f] * inv + bl[col + f] + rrow[f];

    if (DO_BN) {
#pragma unroll
        for (int f = 0; f < F; f++) {
            float gm = bng[col + f], bt = bnb[col + f];
            float mm = bnm[col + f], vv = bnv[col + f];
            o[f] = fmaxf((o[f] - mm) * (gm * rsqrtf(vv + 1e-5f)) + bt, 0.f);
        }
    }

    float* wptr = TO_OUT ? &out[(size_t)node * DOUT + col]
                         : &g_h[(size_t)node * DOUT + col];
    if (F == 4)
        *reinterpret_cast<float4*>(wptr) = make_float4(o[0], o[1], o[2], o[3]);
    else
        *reinterpret_cast<float2*>(wptr) = make_float2(o[0], o[1]);
}

// ---------------- launch ----------------
extern "C" void kernel_launch(void* const* d_in, const int* in_sizes, int n_in,
                              void* d_out, int out_size) {
    const float* x   = (const float*)d_in[0];
    const void*  ei  = d_in[1];
    const float* Wl0 = (const float*)d_in[2];
    const float* Wr0 = (const float*)d_in[3];
    const float* bl0 = (const float*)d_in[4];
    const float* Wl1 = (const float*)d_in[5];
    const float* Wr1 = (const float*)d_in[6];
    const float* bl1 = (const float*)d_in[7];
    const float* Wl2 = (const float*)d_in[8];
    const float* Wr2 = (const float*)d_in[9];
    const float* bl2 = (const float*)d_in[10];
    const float* g0 = (const float*)d_in[11];
    const float* b0 = (const float*)d_in[12];
    const float* m0 = (const float*)d_in[13];
    const float* v0 = (const float*)d_in[14];
    const float* g1 = (const float*)d_in[15];
    const float* b1 = (const float*)d_in[16];
    const float* m1 = (const float*)d_in[17];
    const float* v1 = (const float*)d_in[18];
    float* out = (float*)d_out;

    const int N = in_sizes[0] / 128;
    const int E = in_sizes[1] / 2;
    const int nb = (N + 1023) / 1024;

    // ---- CSR build (shared by all 3 layers) ----
    detect_kernel<<<1, 32>>>((const int*)ei);
    zero_deg_kernel<<<(N + 255) / 256, 256>>>(N);
    convert_kernel<<<(E + 255) / 256, 256>>>(ei, E, N);
    scan_local_kernel<<<nb, 1024>>>(N);
    scan_bsums_kernel<<<1, 32>>>(nb, N);
    scan_add_kernel<<<nb, 1024>>>(N);
    csr_fill_kernel<<<(E + 255) / 256, 256>>>(E);

    dim3 gemmGridWide((N + 127) / 128, 2);
    dim3 gemmGridNarrow((N + 127) / 128, 1);
    int gatherBlocks = (N + 7) / 8;  // 8 warps per block

    // ---- layer 0: x -> g_h (BN + ReLU) ----
    concat_kernel<<<(256 * 128 + 255) / 256, 256>>>(Wl0, Wr0, 128);
    gemm_tc_kernel<256, false><<<gemmGridWide, 256>>>(x, N);
    gather_kernel<128, true, false><<<gatherBlocks, 256>>>(bl0, g0, b0, m0, v0, nullptr, N);

    // ---- layer 1: g_h -> g_h (BN + ReLU) ----
    concat_kernel<<<(256 * 128 + 255) / 256, 256>>>(Wl1, Wr1, 128);
    gemm_tc_kernel<256, true><<<gemmGridWide, 256>>>(nullptr, N);
    gather_kernel<128, true, false><<<gatherBlocks, 256>>>(bl1, g1, b1, m1, v1, nullptr, N);

    // ---- layer 2: g_h -> out (no BN/ReLU) ----
    concat_kernel<<<(128 * 128 + 255) / 256, 256>>>(Wl2, Wr2, 64);
    gemm_tc_kernel<128, true><<<gemmGridNarrow, 256>>>(nullptr, N);
    gather_kernel<64, false, true><<<gatherBlocks, 256>>>(bl2, nullptr, nullptr, nullptr, nullptr, out, N);
}

// round 11
// speedup vs baseline: 4.8043x; 1.0840x over previous
#include <cuda_runtime.h>
#include <cuda_fp16.h>
#include <cstdint>

#define NN 100000
#define EE 1600000

// ---------------- scratch (device globals; no allocation allowed) ----------------
__device__ __half g_Bh[256 * 128];                 // concatenated [Wl | Wr], N-major: g_Bh[j*128+k], fp16
__device__ __half g_T[(size_t)NN * 128];           // GEMM out T-part (h@Wl), fp16
__device__ __half g_R[(size_t)NN * 128];           // GEMM out R-part (h@Wr), fp16
__device__ __half g_h[(size_t)NN * 128];           // hidden activations, fp16
__device__ float  g_inv[NN];                       // 1 / max(deg, 1)
__device__ int    g_degi[NN];
__device__ int    g_off[NN + 1];                   // CSR offsets (by dst)
__device__ int    g_cursor[NN];
__device__ int    g_csr[EE];                       // src ids grouped by dst
__device__ int    g_src[EE];
__device__ int    g_dst[EE];
__device__ int    g_bsum[256];                     // per-block scan sums
__device__ int    g_is64;

__device__ __forceinline__ uint32_t h2_to_u32(__half2 h) {
    return *reinterpret_cast<uint32_t*>(&h);
}

// ---------------- init: zero degrees + dtype detect ----------------
__global__ void init_kernel(const int* __restrict__ ei32, int n) {
    int i = blockIdx.x * blockDim.x + threadIdx.x;
    if (i < n) g_degi[i] = 0;
    if (i == 0) {
        int is64 = 1;
        for (int q = 0; q < 64; q++) {
            if (ei32[2 * q + 1] != 0) { is64 = 0; break; }
        }
        g_is64 = is64;
    }
}

__global__ void convert_kernel(const void* __restrict__ ei, int E, int N) {
    int e = blockIdx.x * blockDim.x + threadIdx.x;
    if (e >= E) return;
    int s, d;
    if (g_is64) {
        const long long* p = (const long long*)ei;
        s = (int)p[e];
        d = (int)p[(size_t)E + e];
    } else {
        const int* p = (const int*)ei;
        s = p[e];
        d = p[E + e];
    }
    s = min(max(s, 0), N - 1);
    d = min(max(d, 0), N - 1);
    g_src[e] = s;
    g_dst[e] = d;
    atomicAdd(&g_degi[d], 1);
}

// ---------------- parallel 3-phase exclusive scan ----------------
__global__ __launch_bounds__(1024) void scan_local_kernel(int n) {
    __shared__ int warp_sums[32];
    const int lane = threadIdx.x & 31;
    const int wid  = threadIdx.x >> 5;
    int i = blockIdx.x * 1024 + threadIdx.x;
    int v = (i < n) ? g_degi[i] : 0;
    int x = v;
#pragma unroll
    for (int o = 1; o < 32; o <<= 1) {
        int y = __shfl_up_sync(0xffffffffu, x, o);
        if (lane >= o) x += y;
    }
    if (lane == 31) warp_sums[wid] = x;
    __syncthreads();
    if (wid == 0) {
        int w = warp_sums[lane];
#pragma unroll
        for (int o = 1; o < 32; o <<= 1) {
            int y = __shfl_up_sync(0xffffffffu, w, o);
            if (lane >= o) w += y;
        }
        warp_sums[lane] = w;
    }
    __syncthreads();
    int incl = x + (wid > 0 ? warp_sums[wid - 1] : 0);
    if (i < n) g_off[i] = incl - v;  // block-local exclusive
    if (threadIdx.x == 1023) g_bsum[blockIdx.x] = incl;
}

__global__ void scan_bsums_kernel(int nb, int n) {
    if (threadIdx.x == 0 && blockIdx.x == 0) {
        int run = 0;
        for (int b = 0; b < nb; b++) {
            int t = g_bsum[b];
            g_bsum[b] = run;
            run += t;
        }
        g_off[n] = run;
    }
}

__global__ __launch_bounds__(1024) void scan_add_kernel(int n) {
    int i = blockIdx.x * 1024 + threadIdx.x;
    if (i >= n) return;
    int off = g_off[i] + g_bsum[blockIdx.x];
    g_off[i] = off;
    g_cursor[i] = off;
    g_inv[i] = 1.0f / fmaxf((float)g_degi[i], 1.0f);
}

__global__ void csr_fill_kernel(int E) {
    int e = blockIdx.x * blockDim.x + threadIdx.x;
    if (e >= E) return;
    int d = g_dst[e];
    int pos = atomicAdd(&g_cursor[d], 1);
    g_csr[pos] = g_src[e];
}

// weights -> fp16, N-major layout g_Bh[j][k]
__global__ void concat_kernel(const float* __restrict__ Wl, const float* __restrict__ Wr, int dout) {
    int W = 2 * dout;
    int id = blockIdx.x * blockDim.x + threadIdx.x;
    if (id < W * 128) {
        int j = id >> 7, k = id & 127;
        float v = (j < dout) ? Wl[k * dout + j] : Wr[k * dout + (j - dout)];
        g_Bh[id] = __float2half_rn(v);
    }
}

// ---------------- fp16 tensor-core GEMM (software pipelined) ----------------
// C[N,W] = A[N,128] @ B[128,W]; T half of columns -> g_T, R half -> g_R (both fp16).
// 128x128 block tile, 8 warps of 32(M)x64(N), mma.m16n8k16 f16.f16.f32.
// USE_H: A = g_h (fp16, raw copy). Else A = Aext (fp32, converts on stage).
template<int W, bool USE_H>
__global__ __launch_bounds__(256) void gemm_tc_kernel(const float* __restrict__ Aext, int nrows) {
    constexpr int DOUT = W / 2;
    __shared__ __half As[128][40];
    __shared__ __half Bs[128][40];

    const int bm = blockIdx.x * 128;
    const int bn = blockIdx.y * 128;
    const int t = threadIdx.x;
    const int lane = t & 31;
    const int wid = t >> 5;
    const int warpM = wid & 3;
    const int warpN = wid >> 2;
    const int g = lane >> 2;
    const int tig = lane & 3;

    // staging mappings: row = t>>1 (0..127), k-half = (t&1)*16
    const int srow = t >> 1;
    const int skoff = (t & 1) * 16;

    float acc[2][8][4];
#pragma unroll
    for (int mt = 0; mt < 2; mt++)
#pragma unroll
        for (int nt = 0; nt < 8; nt++)
#pragma unroll
            for (int c = 0; c < 4; c++) acc[mt][nt][c] = 0.f;

    const bool arow_ok = (bm + srow) < nrows;
    const float*  afptr = Aext ? (Aext + (size_t)(bm + srow) * 128 + skoff) : nullptr;
    const __half* ahptr = (const __half*)g_h + (size_t)(bm + srow) * 128 + skoff;
    const __half* bptr  = g_Bh + (size_t)(bn + srow) * 128 + skoff;

    uint4 aStage[2];   // 16 halves staged per thread per chunk
    uint4 bReg[2];

    auto loadA = [&](int kc) {
        if (USE_H) {
            if (arow_ok) {
                aStage[0] = *reinterpret_cast<const uint4*>(ahptr + kc);
                aStage[1] = *reinterpret_cast<const uint4*>(ahptr + kc + 8);
            } else {
                aStage[0] = make_uint4(0, 0, 0, 0);
                aStage[1] = make_uint4(0, 0, 0, 0);
            }
        } else {
            float4 f[4];
#pragma unroll
            for (int i = 0; i < 4; i++)
                f[i] = arow_ok ? *reinterpret_cast<const float4*>(afptr + kc + i * 4)
                               : make_float4(0.f, 0.f, 0.f, 0.f);
            aStage[0].x = h2_to_u32(__floats2half2_rn(f[0].x, f[0].y));
            aStage[0].y = h2_to_u32(__floats2half2_rn(f[0].z, f[0].w));
            aStage[0].z = h2_to_u32(__floats2half2_rn(f[1].x, f[1].y));
            aStage[0].w = h2_to_u32(__floats2half2_rn(f[1].z, f[1].w));
            aStage[1].x = h2_to_u32(__floats2half2_rn(f[2].x, f[2].y));
            aStage[1].y = h2_to_u32(__floats2half2_rn(f[2].z, f[2].w));
            aStage[1].z = h2_to_u32(__floats2half2_rn(f[3].x, f[3].y));
            aStage[1].w = h2_to_u32(__floats2half2_rn(f[3].z, f[3].w));
        }
    };

    // prologue: load chunk 0
    loadA(0);
    bReg[0] = *reinterpret_cast<const uint4*>(bptr);
    bReg[1] = *reinterpret_cast<const uint4*>(bptr + 8);

    for (int kc = 0; kc < 128; kc += 32) {
        *reinterpret_cast<uint4*>(&As[srow][skoff])     = aStage[0];
        *reinterpret_cast<uint4*>(&As[srow][skoff + 8]) = aStage[1];
        *reinterpret_cast<uint4*>(&Bs[srow][skoff])     = bReg[0];
        *reinterpret_cast<uint4*>(&Bs[srow][skoff + 8]) = bReg[1];
        __syncthreads();

        // prefetch next chunk (overlaps with MMA below)
        if (kc + 32 < 128) {
            loadA(kc + 32);
            bReg[0] = *reinterpret_cast<const uint4*>(bptr + kc + 32);
            bReg[1] = *reinterpret_cast<const uint4*>(bptr + kc + 32 + 8);
        }

#pragma unroll
        for (int ks = 0; ks < 2; ks++) {
            const int kk = ks * 16;
            uint32_t a[2][4], b[8][2];
#pragma unroll
            for (int mt = 0; mt < 2; mt++) {
                int m0 = warpM * 32 + mt * 16 + g;
                a[mt][0] = *reinterpret_cast<const uint32_t*>(&As[m0][kk + 2 * tig]);
                a[mt][1] = *reinterpret_cast<const uint32_t*>(&As[m0 + 8][kk + 2 * tig]);
                a[mt][2] = *reinterpret_cast<const uint32_t*>(&As[m0][kk + 2 * tig + 8]);
                a[mt][3] = *reinterpret_cast<const uint32_t*>(&As[m0 + 8][kk + 2 * tig + 8]);
            }
#pragma unroll
            for (int nt = 0; nt < 8; nt++) {
                int n0 = warpN * 64 + nt * 8 + g;
                b[nt][0] = *reinterpret_cast<const uint32_t*>(&Bs[n0][kk + 2 * tig]);
                b[nt][1] = *reinterpret_cast<const uint32_t*>(&Bs[n0][kk + 2 * tig + 8]);
            }
#pragma unroll
            for (int mt = 0; mt < 2; mt++)
#pragma unroll
                for (int nt = 0; nt < 8; nt++) {
                    asm volatile(
                        "mma.sync.aligned.m16n8k16.row.col.f32.f16.f16.f32 "
                        "{%0,%1,%2,%3}, {%4,%5,%6,%7}, {%8,%9}, {%0,%1,%2,%3};"
                        : "+f"(acc[mt][nt][0]), "+f"(acc[mt][nt][1]),
                          "+f"(acc[mt][nt][2]), "+f"(acc[mt][nt][3])
                        : "r"(a[mt][0]), "r"(a[mt][1]), "r"(a[mt][2]), "r"(a[mt][3]),
                          "r"(b[nt][0]), "r"(b[nt][1]));
                }
        }
        __syncthreads();
    }

    // store: both halves fp16; warp's 64-wide range aligns with DOUT multiples.
    const int gn0 = bn + warpN * 64;
    __half* obase = (gn0 < DOUT) ? (g_T + gn0) : (g_R + (gn0 - DOUT));
#pragma unroll
    for (int mt = 0; mt < 2; mt++) {
        int mrow0 = bm + warpM * 32 + mt * 16 + g;
#pragma unroll
        for (int hf = 0; hf < 2; hf++) {
            int row = mrow0 + hf * 8;
            if (row < nrows) {
                __half* orow = obase + (size_t)row * DOUT;
#pragma unroll
                for (int nt = 0; nt < 8; nt++) {
                    __half2 hv = __floats2half2_rn(acc[mt][nt][hf * 2 + 0],
                                                   acc[mt][nt][hf * 2 + 1]);
                    *reinterpret_cast<__half2*>(&orow[nt * 8 + 2 * tig]) = hv;
                }
            }
        }
    }
}

// ---------------- fused gather + epilogue: warp per dst node ----------------
// out[node] = (sum_{src} g_T[src]) * inv + bl + g_R[node]  [+ BN + ReLU]
template<int DOUT, bool DO_BN, bool TO_OUT>
__global__ __launch_bounds__(256) void gather_kernel(
    const float* __restrict__ bl,
    const float* __restrict__ bng, const float* __restrict__ bnb,
    const float* __restrict__ bnm, const float* __restrict__ bnv,
    float* __restrict__ out, int n) {
    constexpr int F = DOUT / 32;  // values per lane: 4 or 2
    int node = blockIdx.x * (blockDim.x >> 5) + (threadIdx.x >> 5);
    if (node >= n) return;
    int lane = threadIdx.x & 31;
    const int col = lane * F;

    float acc[F];
#pragma unroll
    for (int f = 0; f < F; f++) acc[f] = 0.f;

    int p = g_off[node];
    const int end = g_off[node + 1];

    // unroll by 4 for memory-level parallelism
    for (; p + 4 <= end; p += 4) {
        int s0 = g_csr[p], s1 = g_csr[p + 1], s2 = g_csr[p + 2], s3 = g_csr[p + 3];
        if (F == 4) {
            uint2 r0 = *reinterpret_cast<const uint2*>(&g_T[(size_t)s0 * DOUT + col]);
            uint2 r1 = *reinterpret_cast<const uint2*>(&g_T[(size_t)s1 * DOUT + col]);
            uint2 r2 = *reinterpret_cast<const uint2*>(&g_T[(size_t)s2 * DOUT + col]);
            uint2 r3 = *reinterpret_cast<const uint2*>(&g_T[(size_t)s3 * DOUT + col]);
#pragma unroll
            for (int q = 0; q < 4; q++) {
                uint2 r = (q == 0) ? r0 : (q == 1) ? r1 : (q == 2) ? r2 : r3;
                float2 a0 = __half22float2(*reinterpret_cast<__half2*>(&r.x));
                float2 a1 = __half22float2(*reinterpret_cast<__half2*>(&r.y));
                acc[0] += a0.x; acc[1] += a0.y; acc[2] += a1.x; acc[3] += a1.y;
            }
        } else {
            __half2 h0 = *reinterpret_cast<const __half2*>(&g_T[(size_t)s0 * DOUT + col]);
            __half2 h1 = *reinterpret_cast<const __half2*>(&g_T[(size_t)s1 * DOUT + col]);
            __half2 h2 = *reinterpret_cast<const __half2*>(&g_T[(size_t)s2 * DOUT + col]);
            __half2 h3 = *reinterpret_cast<const __half2*>(&g_T[(size_t)s3 * DOUT + col]);
            float2 a0 = __half22float2(h0), a1 = __half22float2(h1);
            float2 a2 = __half22float2(h2), a3 = __half22float2(h3);
            acc[0] += a0.x + a1.x + a2.x + a3.x;
            acc[1] += a0.y + a1.y + a2.y + a3.y;
        }
    }
    for (; p < end; p++) {
        int s0 = g_csr[p];
        if (F == 4) {
            uint2 r0 = *reinterpret_cast<const uint2*>(&g_T[(size_t)s0 * DOUT + col]);
            float2 a0 = __half22float2(*reinterpret_cast<__half2*>(&r0.x));
            float2 a1 = __half22float2(*reinterpret_cast<__half2*>(&r0.y));
            acc[0] += a0.x; acc[1] += a0.y; acc[2] += a1.x; acc[3] += a1.y;
        } else {
            __half2 h0 = *reinterpret_cast<const __half2*>(&g_T[(size_t)s0 * DOUT + col]);
            float2 a0 = __half22float2(h0);
            acc[0] += a0.x; acc[1] += a0.y;
        }
    }

    const float inv = g_inv[node];
    float o[F];
    // R row (fp16)
    float rv[F];
    {
        const __half* rrow = &g_R[(size_t)node * DOUT + col];
        if (F == 4) {
            uint2 r = *reinterpret_cast<const uint2*>(rrow);
            float2 a0 = __half22float2(*reinterpret_cast<__half2*>(&r.x));
            float2 a1 = __half22float2(*reinterpret_cast<__half2*>(&r.y));
            rv[0] = a0.x; rv[1] = a0.y; rv[2] = a1.x; rv[3] = a1.y;
        } else {
            float2 a0 = __half22float2(*reinterpret_cast<const __half2*>(rrow));
            rv[0] = a0.x; rv[1] = a0.y;
        }
    }
#pragma unroll
    for (int f = 0; f < F; f++)
        o[f] = acc[f] * inv + bl[col + f] + rv[f];

    if (DO_BN) {
#pragma unroll
        for (int f = 0; f < F; f++) {
            float gm = bng[col + f], bt = bnb[col + f];
            float mm = bnm[col + f], vv = bnv[col + f];
            o[f] = fmaxf((o[f] - mm) * (gm * rsqrtf(vv + 1e-5f)) + bt, 0.f);
        }
    }

    if (TO_OUT) {
        float* wptr = &out[(size_t)node * DOUT + col];
        if (F == 4)
            *reinterpret_cast<float4*>(wptr) = make_float4(o[0], o[1], o[2], o[3]);
        else
            *reinterpret_cast<float2*>(wptr) = make_float2(o[0], o[1]);
    } else {
        __half* wptr = &g_h[(size_t)node * DOUT + col];
        if (F == 4) {
            uint2 u;
            u.x = h2_to_u32(__floats2half2_rn(o[0], o[1]));
            u.y = h2_to_u32(__floats2half2_rn(o[2], o[3]));
            *reinterpret_cast<uint2*>(wptr) = u;
        } else {
            *reinterpret_cast<__half2*>(wptr) = __floats2half2_rn(o[0], o[1]);
        }
    }
}

// ---------------- launch ----------------
extern "C" void kernel_launch(void* const* d_in, const int* in_sizes, int n_in,
                              void* d_out, int out_size) {
    const float* x   = (const float*)d_in[0];
    const void*  ei  = d_in[1];
    const float* Wl0 = (const float*)d_in[2];
    const float* Wr0 = (const float*)d_in[3];
    const float* bl0 = (const float*)d_in[4];
    const float* Wl1 = (const float*)d_in[5];
    const float* Wr1 = (const float*)d_in[6];
    const float* bl1 = (const float*)d_in[7];
    const float* Wl2 = (const float*)d_in[8];
    const float* Wr2 = (const float*)d_in[9];
    const float* bl2 = (const float*)d_in[10];
    const float* g0 = (const float*)d_in[11];
    const float* b0 = (const float*)d_in[12];
    const float* m0 = (const float*)d_in[13];
    const float* v0 = (const float*)d_in[14];
    const float* g1 = (const float*)d_in[15];
    const float* b1 = (const float*)d_in[16];
    const float* m1 = (const float*)d_in[17];
    const float* v1 = (const float*)d_in[18];
    float* out = (float*)d_out;

    const int N = in_sizes[0] / 128;
    const int E = in_sizes[1] / 2;
    const int nb = (N + 1023) / 1024;

    // ---- CSR build (shared by all 3 layers) ----
    init_kernel<<<(N + 255) / 256, 256>>>((const int*)ei, N);
    convert_kernel<<<(E + 255) / 256, 256>>>(ei, E, N);
    scan_local_kernel<<<nb, 1024>>>(N);
    scan_bsums_kernel<<<1, 32>>>(nb, N);
    scan_add_kernel<<<nb, 1024>>>(N);
    csr_fill_kernel<<<(E + 255) / 256, 256>>>(E);

    dim3 gemmGridWide((N + 127) / 128, 2);
    dim3 gemmGridNarrow((N + 127) / 128, 1);
    int gatherBlocks = (N + 7) / 8;  // 8 warps per block

    // ---- layer 0: x -> g_h (BN + ReLU) ----
    concat_kernel<<<(256 * 128 + 255) / 256, 256>>>(Wl0, Wr0, 128);
    gemm_tc_kernel<256, false><<<gemmGridWide, 256>>>(x, N);
    gather_kernel<128, true, false><<<gatherBlocks, 256>>>(bl0, g0, b0, m0, v0, nullptr, N);

    // ---- layer 1: g_h -> g_h (BN + ReLU) ----
    concat_kernel<<<(256 * 128 + 255) / 256, 256>>>(Wl1, Wr1, 128);
    gemm_tc_kernel<256, true><<<gemmGridWide, 256>>>(nullptr, N);
    gather_kernel<128, true, false><<<gatherBlocks, 256>>>(bl1, g1, b1, m1, v1, nullptr, N);

    // ---- layer 2: g_h -> out (no BN/ReLU) ----
    concat_kernel<<<(128 * 128 + 255) / 256, 256>>>(Wl2, Wr2, 64);
    gemm_tc_kernel<128, true><<<gemmGridNarrow, 256>>>(nullptr, N);
    gather_kernel<64, false, true><<<gatherBlocks, 256>>>(bl2, nullptr, nullptr, nullptr, nullptr, out, N);
}

// round 13
// speedup vs baseline: 4.9461x; 1.0295x over previous
#include <cuda_runtime.h>
#include <cuda_fp16.h>
#include <cstdint>

#define NN 100000
#define EE 1600000

// ---------------- scratch (device globals; no allocation allowed) ----------------
__device__ __half g_Bh0[256 * 128];                // layer0 [Wl|Wr], N-major fp16
__device__ __half g_Bh1[256 * 128];                // layer1
__device__ __half g_Bh2[128 * 128];                // layer2
__device__ __half g_T[(size_t)NN * 128];           // GEMM out T-part (h@Wl), fp16
__device__ __half g_R[(size_t)NN * 128];           // GEMM out R-part (h@Wr), fp16
__device__ __half g_h[(size_t)NN * 128];           // hidden activations, fp16
__device__ float  g_inv[NN];                       // 1 / max(deg, 1)
__device__ int    g_degi[NN];
__device__ int    g_off[NN + 1];                   // CSR offsets (by dst)
__device__ int    g_cursor[NN];
__device__ int    g_csr[EE];                       // src ids grouped by dst
__device__ int    g_src[EE];
__device__ int    g_dst[EE];
__device__ int    g_bsum[256];                     // per-block scan sums
__device__ int    g_is64;

__device__ __forceinline__ uint32_t h2_to_u32(__half2 h) {
    return *reinterpret_cast<uint32_t*>(&h);
}

// ---------------- init: zero degrees + dtype detect ----------------
__global__ void init_kernel(const int* __restrict__ ei32, int n) {
    int i = blockIdx.x * blockDim.x + threadIdx.x;
    if (i < n) g_degi[i] = 0;
    if (i == 0) {
        int is64 = 1;
        for (int q = 0; q < 64; q++) {
            if (ei32[2 * q + 1] != 0) { is64 = 0; break; }
        }
        g_is64 = is64;
    }
}

__global__ void convert_kernel(const void* __restrict__ ei, int E, int N) {
    int e = blockIdx.x * blockDim.x + threadIdx.x;
    if (e >= E) return;
    int s, d;
    if (g_is64) {
        const long long* p = (const long long*)ei;
        s = (int)p[e];
        d = (int)p[(size_t)E + e];
    } else {
        const int* p = (const int*)ei;
        s = p[e];
        d = p[E + e];
    }
    s = min(max(s, 0), N - 1);
    d = min(max(d, 0), N - 1);
    g_src[e] = s;
    g_dst[e] = d;
    atomicAdd(&g_degi[d], 1);
}

// ---------------- parallel 3-phase exclusive scan ----------------
__global__ __launch_bounds__(1024) void scan_local_kernel(int n) {
    __shared__ int warp_sums[32];
    const int lane = threadIdx.x & 31;
    const int wid  = threadIdx.x >> 5;
    int i = blockIdx.x * 1024 + threadIdx.x;
    int v = (i < n) ? g_degi[i] : 0;
    int x = v;
#pragma unroll
    for (int o = 1; o < 32; o <<= 1) {
        int y = __shfl_up_sync(0xffffffffu, x, o);
        if (lane >= o) x += y;
    }
    if (lane == 31) warp_sums[wid] = x;
    __syncthreads();
    if (wid == 0) {
        int w = warp_sums[lane];
#pragma unroll
        for (int o = 1; o < 32; o <<= 1) {
            int y = __shfl_up_sync(0xffffffffu, w, o);
            if (lane >= o) w += y;
        }
        warp_sums[lane] = w;
    }
    __syncthreads();
    int incl = x + (wid > 0 ? warp_sums[wid - 1] : 0);
    if (i < n) g_off[i] = incl - v;  // block-local exclusive
    if (threadIdx.x == 1023) g_bsum[blockIdx.x] = incl;
}

// parallel scan of up to 128 block sums
__global__ void scan_bsums_kernel(int nb, int n) {
    __shared__ int ws[4];
    const int i = threadIdx.x;        // 0..127
    const int lane = i & 31;
    const int w = i >> 5;
    int v = (i < nb) ? g_bsum[i] : 0;
    int x = v;
#pragma unroll
    for (int o = 1; o < 32; o <<= 1) {
        int y = __shfl_up_sync(0xffffffffu, x, o);
        if (lane >= o) x += y;
    }
    if (lane == 31) ws[w] = x;
    __syncthreads();
    int woff = 0;
#pragma unroll
    for (int q = 0; q < 4; q++) if (q < w) woff += ws[q];
    int incl = x + woff;
    if (i < nb) g_bsum[i] = incl - v;   // exclusive
    if (i == 127) g_off[n] = incl;      // grand total
}

__global__ __launch_bounds__(1024) void scan_add_kernel(int n) {
    int i = blockIdx.x * 1024 + threadIdx.x;
    if (i >= n) return;
    int off = g_off[i] + g_bsum[blockIdx.x];
    g_off[i] = off;
    g_cursor[i] = off;
    g_inv[i] = 1.0f / fmaxf((float)g_degi[i], 1.0f);
}

__global__ void csr_fill_kernel(int E) {
    int e = blockIdx.x * blockDim.x + threadIdx.x;
    if (e >= E) return;
    int d = g_dst[e];
    int pos = atomicAdd(&g_cursor[d], 1);
    g_csr[pos] = g_src[e];
}

// all three layers' weights -> fp16, N-major g_Bh*[j][k], one kernel
__global__ void concat_all_kernel(
    const float* __restrict__ Wl0, const float* __restrict__ Wr0,
    const float* __restrict__ Wl1, const float* __restrict__ Wr1,
    const float* __restrict__ Wl2, const float* __restrict__ Wr2) {
    int id = blockIdx.x * blockDim.x + threadIdx.x;
    if (id < 32768) {
        int j = id >> 7, k = id & 127;
        float v = (j < 128) ? Wl0[k * 128 + j] : Wr0[k * 128 + (j - 128)];
        g_Bh0[id] = __float2half_rn(v);
    } else if (id < 65536) {
        int t2 = id - 32768;
        int j = t2 >> 7, k = t2 & 127;
        float v = (j < 128) ? Wl1[k * 128 + j] : Wr1[k * 128 + (j - 128)];
        g_Bh1[t2] = __float2half_rn(v);
    } else if (id < 81920) {
        int t2 = id - 65536;
        int j = t2 >> 7, k = t2 & 127;
        float v = (j < 64) ? Wl2[k * 64 + j] : Wr2[k * 64 + (j - 64)];
        g_Bh2[t2] = __float2half_rn(v);
    }
}

// ---------------- fp16 tensor-core GEMM (software pipelined) ----------------
// C[N,W] = A[N,128] @ B[128,W]; T half of columns -> g_T, R half -> g_R (both fp16).
// 128x128 block tile, 8 warps of 32(M)x64(N), mma.m16n8k16 f16.f16.f32.
// USE_H: A = g_h (fp16, raw copy). Else A = Aext (fp32, converts on stage).
template<int W, bool USE_H, int LAYER>
__global__ __launch_bounds__(256) void gemm_tc_kernel(const float* __restrict__ Aext, int nrows) {
    constexpr int DOUT = W / 2;
    __shared__ __half As[128][40];
    __shared__ __half Bs[128][40];

    const __half* __restrict__ Bw =
        (LAYER == 0) ? (const __half*)g_Bh0 :
        (LAYER == 1) ? (const __half*)g_Bh1 : (const __half*)g_Bh2;

    const int bm = blockIdx.x * 128;
    const int bn = blockIdx.y * 128;
    const int t = threadIdx.x;
    const int lane = t & 31;
    const int wid = t >> 5;
    const int warpM = wid & 3;
    const int warpN = wid >> 2;
    const int g = lane >> 2;
    const int tig = lane & 3;

    // staging mappings: row = t>>1 (0..127), k-half = (t&1)*16
    const int srow = t >> 1;
    const int skoff = (t & 1) * 16;

    float acc[2][8][4];
#pragma unroll
    for (int mt = 0; mt < 2; mt++)
#pragma unroll
        for (int nt = 0; nt < 8; nt++)
#pragma unroll
            for (int c = 0; c < 4; c++) acc[mt][nt][c] = 0.f;

    const bool arow_ok = (bm + srow) < nrows;
    const float*  afptr = Aext ? (Aext + (size_t)(bm + srow) * 128 + skoff) : nullptr;
    const __half* ahptr = (const __half*)g_h + (size_t)(bm + srow) * 128 + skoff;
    const __half* bptr  = Bw + (size_t)(bn + srow) * 128 + skoff;

    uint4 aStage[2];   // 16 halves staged per thread per chunk
    uint4 bReg[2];

    auto loadA = [&](int kc) {
        if (USE_H) {
            if (arow_ok) {
                aStage[0] = *reinterpret_cast<const uint4*>(ahptr + kc);
                aStage[1] = *reinterpret_cast<const uint4*>(ahptr + kc + 8);
            } else {
                aStage[0] = make_uint4(0, 0, 0, 0);
                aStage[1] = make_uint4(0, 0, 0, 0);
            }
        } else {
            float4 f[4];
#pragma unroll
            for (int i = 0; i < 4; i++)
                f[i] = arow_ok ? *reinterpret_cast<const float4*>(afptr + kc + i * 4)
                               : make_float4(0.f, 0.f, 0.f, 0.f);
            aStage[0].x = h2_to_u32(__floats2half2_rn(f[0].x, f[0].y));
            aStage[0].y = h2_to_u32(__floats2half2_rn(f[0].z, f[0].w));
            aStage[0].z = h2_to_u32(__floats2half2_rn(f[1].x, f[1].y));
            aStage[0].w = h2_to_u32(__floats2half2_rn(f[1].z, f[1].w));
            aStage[1].x = h2_to_u32(__floats2half2_rn(f[2].x, f[2].y));
            aStage[1].y = h2_to_u32(__floats2half2_rn(f[2].z, f[2].w));
            aStage[1].z = h2_to_u32(__floats2half2_rn(f[3].x, f[3].y));
            aStage[1].w = h2_to_u32(__floats2half2_rn(f[3].z, f[3].w));
        }
    };

    // prologue: load chunk 0
    loadA(0);
    bReg[0] = *reinterpret_cast<const uint4*>(bptr);
    bReg[1] = *reinterpret_cast<const uint4*>(bptr + 8);

    for (int kc = 0; kc < 128; kc += 32) {
        *reinterpret_cast<uint4*>(&As[srow][skoff])     = aStage[0];
        *reinterpret_cast<uint4*>(&As[srow][skoff + 8]) = aStage[1];
        *reinterpret_cast<uint4*>(&Bs[srow][skoff])     = bReg[0];
        *reinterpret_cast<uint4*>(&Bs[srow][skoff + 8]) = bReg[1];
        __syncthreads();

        // prefetch next chunk (overlaps with MMA below)
        if (kc + 32 < 128) {
            loadA(kc + 32);
            bReg[0] = *reinterpret_cast<const uint4*>(bptr + kc + 32);
            bReg[1] = *reinterpret_cast<const uint4*>(bptr + kc + 32 + 8);
        }

#pragma unroll
        for (int ks = 0; ks < 2; ks++) {
            const int kk = ks * 16;
            uint32_t a[2][4], b[8][2];
#pragma unroll
            for (int mt = 0; mt < 2; mt++) {
                int m0 = warpM * 32 + mt * 16 + g;
                a[mt][0] = *reinterpret_cast<const uint32_t*>(&As[m0][kk + 2 * tig]);
                a[mt][1] = *reinterpret_cast<const uint32_t*>(&As[m0 + 8][kk + 2 * tig]);
                a[mt][2] = *reinterpret_cast<const uint32_t*>(&As[m0][kk + 2 * tig + 8]);
                a[mt][3] = *reinterpret_cast<const uint32_t*>(&As[m0 + 8][kk + 2 * tig + 8]);
            }
#pragma unroll
            for (int nt = 0; nt < 8; nt++) {
                int n0 = warpN * 64 + nt * 8 + g;
                b[nt][0] = *reinterpret_cast<const uint32_t*>(&Bs[n0][kk + 2 * tig]);
                b[nt][1] = *reinterpret_cast<const uint32_t*>(&Bs[n0][kk + 2 * tig + 8]);
            }
#pragma unroll
            for (int mt = 0; mt < 2; mt++)
#pragma unroll
                for (int nt = 0; nt < 8; nt++) {
                    asm volatile(
                        "mma.sync.aligned.m16n8k16.row.col.f32.f16.f16.f32 "
                        "{%0,%1,%2,%3}, {%4,%5,%6,%7}, {%8,%9}, {%0,%1,%2,%3};"
                        : "+f"(acc[mt][nt][0]), "+f"(acc[mt][nt][1]),
                          "+f"(acc[mt][nt][2]), "+f"(acc[mt][nt][3])
                        : "r"(a[mt][0]), "r"(a[mt][1]), "r"(a[mt][2]), "r"(a[mt][3]),
                          "r"(b[nt][0]), "r"(b[nt][1]));
                }
        }
        __syncthreads();
    }

    // store: both halves fp16; warp's 64-wide range aligns with DOUT multiples.
    const int gn0 = bn + warpN * 64;
    __half* obase = (gn0 < DOUT) ? (g_T + gn0) : (g_R + (gn0 - DOUT));
#pragma unroll
    for (int mt = 0; mt < 2; mt++) {
        int mrow0 = bm + warpM * 32 + mt * 16 + g;
#pragma unroll
        for (int hf = 0; hf < 2; hf++) {
            int row = mrow0 + hf * 8;
            if (row < nrows) {
                __half* orow = obase + (size_t)row * DOUT;
#pragma unroll
                for (int nt = 0; nt < 8; nt++) {
                    __half2 hv = __floats2half2_rn(acc[mt][nt][hf * 2 + 0],
                                                   acc[mt][nt][hf * 2 + 1]);
                    *reinterpret_cast<__half2*>(&orow[nt * 8 + 2 * tig]) = hv;
                }
            }
        }
    }
}

// ---------------- fused gather + epilogue: warp per dst node ----------------
// out[node] = (sum_{src} g_T[src]) * inv + bl + g_R[node]  [+ BN + ReLU]
template<int DOUT, bool DO_BN, bool TO_OUT>
__global__ __launch_bounds__(256) void gather_kernel(
    const float* __restrict__ bl,
    const float* __restrict__ bng, const float* __restrict__ bnb,
    const float* __restrict__ bnm, const float* __restrict__ bnv,
    float* __restrict__ out, int n) {
    constexpr int F = DOUT / 32;  // values per lane: 4 or 2
    int node = blockIdx.x * (blockDim.x >> 5) + (threadIdx.x >> 5);
    if (node >= n) return;
    int lane = threadIdx.x & 31;
    const int col = lane * F;

    float acc[F];
#pragma unroll
    for (int f = 0; f < F; f++) acc[f] = 0.f;

    int p = g_off[node];
    const int end = g_off[node + 1];

    // unroll by 4 for memory-level parallelism
    for (; p + 4 <= end; p += 4) {
        int s0 = g_csr[p], s1 = g_csr[p + 1], s2 = g_csr[p + 2], s3 = g_csr[p + 3];
        if (F == 4) {
            uint2 r0 = *reinterpret_cast<const uint2*>(&g_T[(size_t)s0 * DOUT + col]);
            uint2 r1 = *reinterpret_cast<const uint2*>(&g_T[(size_t)s1 * DOUT + col]);
            uint2 r2 = *reinterpret_cast<const uint2*>(&g_T[(size_t)s2 * DOUT + col]);
            uint2 r3 = *reinterpret_cast<const uint2*>(&g_T[(size_t)s3 * DOUT + col]);
#pragma unroll
            for (int q = 0; q < 4; q++) {
                uint2 r = (q == 0) ? r0 : (q == 1) ? r1 : (q == 2) ? r2 : r3;
                float2 a0 = __half22float2(*reinterpret_cast<__half2*>(&r.x));
                float2 a1 = __half22float2(*reinterpret_cast<__half2*>(&r.y));
                acc[0] += a0.x; acc[1] += a0.y; acc[2] += a1.x; acc[3] += a1.y;
            }
        } else {
            __half2 h0 = *reinterpret_cast<const __half2*>(&g_T[(size_t)s0 * DOUT + col]);
            __half2 h1 = *reinterpret_cast<const __half2*>(&g_T[(size_t)s1 * DOUT + col]);
            __half2 h2 = *reinterpret_cast<const __half2*>(&g_T[(size_t)s2 * DOUT + col]);
            __half2 h3 = *reinterpret_cast<const __half2*>(&g_T[(size_t)s3 * DOUT + col]);
            float2 a0 = __half22float2(h0), a1 = __half22float2(h1);
            float2 a2 = __half22float2(h2), a3 = __half22float2(h3);
            acc[0] += a0.x + a1.x + a2.x + a3.x;
            acc[1] += a0.y + a1.y + a2.y + a3.y;
        }
    }
    for (; p < end; p++) {
        int s0 = g_csr[p];
        if (F == 4) {
            uint2 r0 = *reinterpret_cast<const uint2*>(&g_T[(size_t)s0 * DOUT + col]);
            float2 a0 = __half22float2(*reinterpret_cast<__half2*>(&r0.x));
            float2 a1 = __half22float2(*reinterpret_cast<__half2*>(&r0.y));
            acc[0] += a0.x; acc[1] += a0.y; acc[2] += a1.x; acc[3] += a1.y;
        } else {
            __half2 h0 = *reinterpret_cast<const __half2*>(&g_T[(size_t)s0 * DOUT + col]);
            float2 a0 = __half22float2(h0);
            acc[0] += a0.x; acc[1] += a0.y;
        }
    }

    const float inv = g_inv[node];
    float o[F];
    // R row (fp16)
    float rv[F];
    {
        const __half* rrow = &g_R[(size_t)node * DOUT + col];
        if (F == 4) {
            uint2 r = *reinterpret_cast<const uint2*>(rrow);
            float2 a0 = __half22float2(*reinterpret_cast<__half2*>(&r.x));
            float2 a1 = __half22float2(*reinterpret_cast<__half2*>(&r.y));
            rv[0] = a0.x; rv[1] = a0.y; rv[2] = a1.x; rv[3] = a1.y;
        } else {
            float2 a0 = __half22float2(*reinterpret_cast<const __half2*>(rrow));
            rv[0] = a0.x; rv[1] = a0.y;
        }
    }
#pragma unroll
    for (int f = 0; f < F; f++)
        o[f] = acc[f] * inv + bl[col + f] + rv[f];

    if (DO_BN) {
#pragma unroll
        for (int f = 0; f < F; f++) {
            float gm = bng[col + f], bt = bnb[col + f];
            float mm = bnm[col + f], vv = bnv[col + f];
            o[f] = fmaxf((o[f] - mm) * (gm * rsqrtf(vv + 1e-5f)) + bt, 0.f);
        }
    }

    if (TO_OUT) {
        float* wptr = &out[(size_t)node * DOUT + col];
        if (F == 4)
            *reinterpret_cast<float4*>(wptr) = make_float4(o[0], o[1], o[2], o[3]);
        else
            *reinterpret_cast<float2*>(wptr) = make_float2(o[0], o[1]);
    } else {
        __half* wptr = &g_h[(size_t)node * DOUT + col];
        if (F == 4) {
            uint2 u;
            u.x = h2_to_u32(__floats2half2_rn(o[0], o[1]));
            u.y = h2_to_u32(__floats2half2_rn(o[2], o[3]));
            *reinterpret_cast<uint2*>(wptr) = u;
        } else {
            *reinterpret_cast<__half2*>(wptr) = __floats2half2_rn(o[0], o[1]);
        }
    }
}

// ---------------- launch ----------------
extern "C" void kernel_launch(void* const* d_in, const int* in_sizes, int n_in,
                              void* d_out, int out_size) {
    const float* x   = (const float*)d_in[0];
    const void*  ei  = d_in[1];
    const float* Wl0 = (const float*)d_in[2];
    const float* Wr0 = (const float*)d_in[3];
    const float* bl0 = (const float*)d_in[4];
    const float* Wl1 = (const float*)d_in[5];
    const float* Wr1 = (const float*)d_in[6];
    const float* bl1 = (const float*)d_in[7];
    const float* Wl2 = (const float*)d_in[8];
    const float* Wr2 = (const float*)d_in[9];
    const float* bl2 = (const float*)d_in[10];
    const float* g0 = (const float*)d_in[11];
    const float* b0 = (const float*)d_in[12];
    const float* m0 = (const float*)d_in[13];
    const float* v0 = (const float*)d_in[14];
    const float* g1 = (const float*)d_in[15];
    const float* b1 = (const float*)d_in[16];
    const float* m1 = (const float*)d_in[17];
    const float* v1 = (const float*)d_in[18];
    float* out = (float*)d_out;

    const int N = in_sizes[0] / 128;
    const int E = in_sizes[1] / 2;
    const int nb = (N + 1023) / 1024;

    // one-time side stream + fork/join events (host objects, no device memory)
    static cudaStream_t s_side = nullptr;
    static cudaEvent_t  s_fork = nullptr, s_join = nullptr;
    if (s_side == nullptr) {
        cudaStreamCreateWithFlags(&s_side, cudaStreamNonBlocking);
        cudaEventCreateWithFlags(&s_fork, cudaEventDisableTiming);
        cudaEventCreateWithFlags(&s_join, cudaEventDisableTiming);
    }

    // ---- fork: CSR build on side stream, weights+GEMM0 on main ----
    cudaEventRecord(s_fork, 0);
    cudaStreamWaitEvent(s_side, s_fork, 0);

    init_kernel<<<(N + 255) / 256, 256, 0, s_side>>>((const int*)ei, N);
    convert_kernel<<<(E + 255) / 256, 256, 0, s_side>>>(ei, E, N);
    scan_local_kernel<<<nb, 1024, 0, s_side>>>(N);
    scan_bsums_kernel<<<1, 128, 0, s_side>>>(nb, N);
    scan_add_kernel<<<nb, 1024, 0, s_side>>>(N);
    csr_fill_kernel<<<(E + 255) / 256, 256, 0, s_side>>>(E);
    cudaEventRecord(s_join, s_side);

    dim3 gemmGridWide((N + 127) / 128, 2);
    dim3 gemmGridNarrow((N + 127) / 128, 1);
    int gatherBlocks = (N + 7) / 8;  // 8 warps per block

    concat_all_kernel<<<(81920 + 255) / 256, 256>>>(Wl0, Wr0, Wl1, Wr1, Wl2, Wr2);
    gemm_tc_kernel<256, false, 0><<<gemmGridWide, 256>>>(x, N);

    // ---- join: gather-0 needs CSR + GEMM0 ----
    cudaStreamWaitEvent(0, s_join, 0);
    gather_kernel<128, true, false><<<gatherBlocks, 256>>>(bl0, g0, b0, m0, v0, nullptr, N);

    // ---- layer 1: g_h -> g_h (BN + ReLU) ----
    gemm_tc_kernel<256, true, 1><<<gemmGridWide, 256>>>(nullptr, N);
    gather_kernel<128, true, false><<<gatherBlocks, 256>>>(bl1, g1, b1, m1, v1, nullptr, N);

    // ---- layer 2: g_h -> out (no BN/ReLU) ----
    gemm_tc_kernel<128, true, 2><<<gemmGridNarrow, 256>>>(nullptr, N);
    gather_kernel<64, false, true><<<gatherBlocks, 256>>>(bl2, nullptr, nullptr, nullptr, nullptr, out, N);
}

// round 14
// speedup vs baseline: 5.0717x; 1.0254x over previous
#include <cuda_runtime.h>
#include <cuda_fp16.h>
#include <cstdint>

#define NN 100000
#define EE 1600000

// ---------------- scratch (device globals; no allocation allowed) ----------------
__device__ __half g_Bh0[256 * 128];                // layer0 [Wl|Wr], N-major fp16
__device__ __half g_Bh1[256 * 128];                // layer1
__device__ __half g_Bh2[128 * 128];                // layer2
__device__ __half g_T[(size_t)NN * 128];           // GEMM out T-part (h@Wl), fp16
__device__ __half g_R[(size_t)NN * 128];           // GEMM out R-part (h@Wr), fp16
__device__ __half g_h[(size_t)NN * 128];           // hidden activations, fp16
__device__ float  g_inv[NN];                       // 1 / max(deg, 1)
__device__ int    g_degi[NN];
__device__ int    g_off[NN + 1];                   // CSR offsets (by dst)
__device__ int    g_cursor[NN];
__device__ int    g_csr[EE];                       // src ids grouped by dst
__device__ int    g_bsum[256];                     // per-block scan sums
__device__ int    g_is64;

__device__ __forceinline__ uint32_t h2_to_u32(__half2 h) {
    return *reinterpret_cast<uint32_t*>(&h);
}

// ---------------- init: zero degrees + dtype detect ----------------
__global__ void init_kernel(const int* __restrict__ ei32, int n) {
    int i = blockIdx.x * blockDim.x + threadIdx.x;
    if (i < n) g_degi[i] = 0;
    if (i == 0) {
        int is64 = 1;
        for (int q = 0; q < 64; q++) {
            if (ei32[2 * q + 1] != 0) { is64 = 0; break; }
        }
        g_is64 = is64;
    }
}

// degree histogram (reads dst half of edge index only)
__global__ void deg_kernel(const void* __restrict__ ei, int E, int N) {
    int e = blockIdx.x * blockDim.x + threadIdx.x;
    if (e >= E) return;
    int d;
    if (g_is64) d = (int)((const long long*)ei)[(size_t)E + e];
    else        d = ((const int*)ei)[E + e];
    d = min(max(d, 0), N - 1);
    atomicAdd(&g_degi[d], 1);
}

// ---------------- parallel 3-phase exclusive scan ----------------
__global__ __launch_bounds__(1024) void scan_local_kernel(int n) {
    __shared__ int warp_sums[32];
    const int lane = threadIdx.x & 31;
    const int wid  = threadIdx.x >> 5;
    int i = blockIdx.x * 1024 + threadIdx.x;
    int v = (i < n) ? g_degi[i] : 0;
    int x = v;
#pragma unroll
    for (int o = 1; o < 32; o <<= 1) {
        int y = __shfl_up_sync(0xffffffffu, x, o);
        if (lane >= o) x += y;
    }
    if (lane == 31) warp_sums[wid] = x;
    __syncthreads();
    if (wid == 0) {
        int w = warp_sums[lane];
#pragma unroll
        for (int o = 1; o < 32; o <<= 1) {
            int y = __shfl_up_sync(0xffffffffu, w, o);
            if (lane >= o) w += y;
        }
        warp_sums[lane] = w;
    }
    __syncthreads();
    int incl = x + (wid > 0 ? warp_sums[wid - 1] : 0);
    if (i < n) g_off[i] = incl - v;  // block-local exclusive
    if (threadIdx.x == 1023) g_bsum[blockIdx.x] = incl;
}

// parallel scan of up to 128 block sums
__global__ void scan_bsums_kernel(int nb, int n) {
    __shared__ int ws[4];
    const int i = threadIdx.x;        // 0..127
    const int lane = i & 31;
    const int w = i >> 5;
    int v = (i < nb) ? g_bsum[i] : 0;
    int x = v;
#pragma unroll
    for (int o = 1; o < 32; o <<= 1) {
        int y = __shfl_up_sync(0xffffffffu, x, o);
        if (lane >= o) x += y;
    }
    if (lane == 31) ws[w] = x;
    __syncthreads();
    int woff = 0;
#pragma unroll
    for (int q = 0; q < 4; q++) if (q < w) woff += ws[q];
    int incl = x + woff;
    if (i < nb) g_bsum[i] = incl - v;   // exclusive
    if (i == 127) g_off[n] = incl;      // grand total
}

__global__ __launch_bounds__(1024) void scan_add_kernel(int n) {
    int i = blockIdx.x * 1024 + threadIdx.x;
    if (i >= n) return;
    int off = g_off[i] + g_bsum[blockIdx.x];
    g_off[i] = off;
    g_cursor[i] = off;
    g_inv[i] = 1.0f / fmaxf((float)g_degi[i], 1.0f);
}

// fill CSR: re-decode edge index directly (no src/dst intermediates)
__global__ void csr_fill_kernel(const void* __restrict__ ei, int E, int N) {
    int e = blockIdx.x * blockDim.x + threadIdx.x;
    if (e >= E) return;
    int s, d;
    if (g_is64) {
        const long long* p = (const long long*)ei;
        s = (int)p[e];
        d = (int)p[(size_t)E + e];
    } else {
        const int* p = (const int*)ei;
        s = p[e];
        d = p[E + e];
    }
    s = min(max(s, 0), N - 1);
    d = min(max(d, 0), N - 1);
    int pos = atomicAdd(&g_cursor[d], 1);
    g_csr[pos] = s;
}

// all three layers' weights -> fp16, N-major g_Bh*[j][k], one kernel
__global__ void concat_all_kernel(
    const float* __restrict__ Wl0, const float* __restrict__ Wr0,
    const float* __restrict__ Wl1, const float* __restrict__ Wr1,
    const float* __restrict__ Wl2, const float* __restrict__ Wr2) {
    int id = blockIdx.x * blockDim.x + threadIdx.x;
    if (id < 32768) {
        int j = id >> 7, k = id & 127;
        float v = (j < 128) ? Wl0[k * 128 + j] : Wr0[k * 128 + (j - 128)];
        g_Bh0[id] = __float2half_rn(v);
    } else if (id < 65536) {
        int t2 = id - 32768;
        int j = t2 >> 7, k = t2 & 127;
        float v = (j < 128) ? Wl1[k * 128 + j] : Wr1[k * 128 + (j - 128)];
        g_Bh1[t2] = __float2half_rn(v);
    } else if (id < 81920) {
        int t2 = id - 65536;
        int j = t2 >> 7, k = t2 & 127;
        float v = (j < 64) ? Wl2[k * 64 + j] : Wr2[k * 64 + (j - 64)];
        g_Bh2[t2] = __float2half_rn(v);
    }
}

// ---------------- fp16 tensor-core GEMM (double-buffered, 1 sync/chunk) ----------------
// C[N,W] = A[N,128] @ B[128,W]; T half of columns -> g_T, R half -> g_R (both fp16).
// 128x128 block tile, 8 warps of 32(M)x64(N), mma.m16n8k16 f16.f16.f32.
template<int W, bool USE_H, int LAYER>
__global__ __launch_bounds__(256) void gemm_tc_kernel(const float* __restrict__ Aext, int nrows) {
    constexpr int DOUT = W / 2;
    __shared__ __half As[2][128][40];
    __shared__ __half Bs[2][128][40];

    const __half* __restrict__ Bw =
        (LAYER == 0) ? (const __half*)g_Bh0 :
        (LAYER == 1) ? (const __half*)g_Bh1 : (const __half*)g_Bh2;

    const int bm = blockIdx.x * 128;
    const int bn = blockIdx.y * 128;
    const int t = threadIdx.x;
    const int lane = t & 31;
    const int wid = t >> 5;
    const int warpM = wid & 3;
    const int warpN = wid >> 2;
    const int g = lane >> 2;
    const int tig = lane & 3;

    const int srow = t >> 1;
    const int skoff = (t & 1) * 16;

    float acc[2][8][4];
#pragma unroll
    for (int mt = 0; mt < 2; mt++)
#pragma unroll
        for (int nt = 0; nt < 8; nt++)
#pragma unroll
            for (int c = 0; c < 4; c++) acc[mt][nt][c] = 0.f;

    const bool arow_ok = (bm + srow) < nrows;
    const float*  afptr = Aext ? (Aext + (size_t)(bm + srow) * 128 + skoff) : nullptr;
    const __half* ahptr = (const __half*)g_h + (size_t)(bm + srow) * 128 + skoff;
    const __half* bptr  = Bw + (size_t)(bn + srow) * 128 + skoff;

    uint4 aStage[2];
    uint4 bReg[2];

    auto loadA = [&](int kc) {
        if (USE_H) {
            if (arow_ok) {
                aStage[0] = *reinterpret_cast<const uint4*>(ahptr + kc);
                aStage[1] = *reinterpret_cast<const uint4*>(ahptr + kc + 8);
            } else {
                aStage[0] = make_uint4(0, 0, 0, 0);
                aStage[1] = make_uint4(0, 0, 0, 0);
            }
        } else {
            float4 f[4];
#pragma unroll
            for (int i = 0; i < 4; i++)
                f[i] = arow_ok ? *reinterpret_cast<const float4*>(afptr + kc + i * 4)
                               : make_float4(0.f, 0.f, 0.f, 0.f);
            aStage[0].x = h2_to_u32(__floats2half2_rn(f[0].x, f[0].y));
            aStage[0].y = h2_to_u32(__floats2half2_rn(f[0].z, f[0].w));
            aStage[0].z = h2_to_u32(__floats2half2_rn(f[1].x, f[1].y));
            aStage[0].w = h2_to_u32(__floats2half2_rn(f[1].z, f[1].w));
            aStage[1].x = h2_to_u32(__floats2half2_rn(f[2].x, f[2].y));
            aStage[1].y = h2_to_u32(__floats2half2_rn(f[2].z, f[2].w));
            aStage[1].z = h2_to_u32(__floats2half2_rn(f[3].x, f[3].y));
            aStage[1].w = h2_to_u32(__floats2half2_rn(f[3].z, f[3].w));
        }
    };
    auto loadB = [&](int kc) {
        bReg[0] = *reinterpret_cast<const uint4*>(bptr + kc);
        bReg[1] = *reinterpret_cast<const uint4*>(bptr + kc + 8);
    };
    auto stage = [&](int buf) {
        *reinterpret_cast<uint4*>(&As[buf][srow][skoff])     = aStage[0];
        *reinterpret_cast<uint4*>(&As[buf][srow][skoff + 8]) = aStage[1];
        *reinterpret_cast<uint4*>(&Bs[buf][srow][skoff])     = bReg[0];
        *reinterpret_cast<uint4*>(&Bs[buf][srow][skoff + 8]) = bReg[1];
    };

    // prologue: chunk 0 -> buf 0
    loadA(0);
    loadB(0);
    stage(0);
    __syncthreads();

#pragma unroll
    for (int it = 0; it < 4; it++) {
        const int cur = it & 1;
        // issue global prefetch of next chunk (latency covered by MMA below)
        if (it < 3) {
            loadA((it + 1) * 32);
            loadB((it + 1) * 32);
        }

#pragma unroll
        for (int ks = 0; ks < 2; ks++) {
            const int kk = ks * 16;
            uint32_t a[2][4], b[8][2];
#pragma unroll
            for (int mt = 0; mt < 2; mt++) {
                int m0 = warpM * 32 + mt * 16 + g;
                a[mt][0] = *reinterpret_cast<const uint32_t*>(&As[cur][m0][kk + 2 * tig]);
                a[mt][1] = *reinterpret_cast<const uint32_t*>(&As[cur][m0 + 8][kk + 2 * tig]);
                a[mt][2] = *reinterpret_cast<const uint32_t*>(&As[cur][m0][kk + 2 * tig + 8]);
                a[mt][3] = *reinterpret_cast<const uint32_t*>(&As[cur][m0 + 8][kk + 2 * tig + 8]);
            }
#pragma unroll
            for (int nt = 0; nt < 8; nt++) {
                int n0 = warpN * 64 + nt * 8 + g;
                b[nt][0] = *reinterpret_cast<const uint32_t*>(&Bs[cur][n0][kk + 2 * tig]);
                b[nt][1] = *reinterpret_cast<const uint32_t*>(&Bs[cur][n0][kk + 2 * tig + 8]);
            }
#pragma unroll
            for (int mt = 0; mt < 2; mt++)
#pragma unroll
                for (int nt = 0; nt < 8; nt++) {
                    asm volatile(
                        "mma.sync.aligned.m16n8k16.row.col.f32.f16.f16.f32 "
                        "{%0,%1,%2,%3}, {%4,%5,%6,%7}, {%8,%9}, {%0,%1,%2,%3};"
                        : "+f"(acc[mt][nt][0]), "+f"(acc[mt][nt][1]),
                          "+f"(acc[mt][nt][2]), "+f"(acc[mt][nt][3])
                        : "r"(a[mt][0]), "r"(a[mt][1]), "r"(a[mt][2]), "r"(a[mt][3]),
                          "r"(b[nt][0]), "r"(b[nt][1]));
                }
        }

        // stage next chunk into the other buffer (safe: reads of that buffer
        // finished before the sync at the end of the previous iteration)
        if (it < 3) stage(cur ^ 1);
        __syncthreads();
    }

    // store: both halves fp16; warp's 64-wide range aligns with DOUT multiples.
    const int gn0 = bn + warpN * 64;
    __half* obase = (gn0 < DOUT) ? (g_T + gn0) : (g_R + (gn0 - DOUT));
#pragma unroll
    for (int mt = 0; mt < 2; mt++) {
        int mrow0 = bm + warpM * 32 + mt * 16 + g;
#pragma unroll
        for (int hf = 0; hf < 2; hf++) {
            int row = mrow0 + hf * 8;
            if (row < nrows) {
                __half* orow = obase + (size_t)row * DOUT;
#pragma unroll
                for (int nt = 0; nt < 8; nt++) {
                    __half2 hv = __floats2half2_rn(acc[mt][nt][hf * 2 + 0],
                                                   acc[mt][nt][hf * 2 + 1]);
                    *reinterpret_cast<__half2*>(&orow[nt * 8 + 2 * tig]) = hv;
                }
            }
        }
    }
}

// ---------------- fused gather + epilogue: warp per dst node ----------------
// out[node] = (sum_{src} g_T[src]) * inv + bl + g_R[node]  [+ BN + ReLU]
template<int DOUT, bool DO_BN, bool TO_OUT>
__global__ __launch_bounds__(256) void gather_kernel(
    const float* __restrict__ bl,
    const float* __restrict__ bng, const float* __restrict__ bnb,
    const float* __restrict__ bnm, const float* __restrict__ bnv,
    float* __restrict__ out, int n) {
    constexpr int F = DOUT / 32;  // values per lane: 4 or 2
    int node = blockIdx.x * (blockDim.x >> 5) + (threadIdx.x >> 5);
    if (node >= n) return;
    int lane = threadIdx.x & 31;
    const int col = lane * F;

    float acc[F];
#pragma unroll
    for (int f = 0; f < F; f++) acc[f] = 0.f;

    int p = g_off[node];
    const int end = g_off[node + 1];

    // unroll by 4 for memory-level parallelism
    for (; p + 4 <= end; p += 4) {
        int s0 = g_csr[p], s1 = g_csr[p + 1], s2 = g_csr[p + 2], s3 = g_csr[p + 3];
        if (F == 4) {
            uint2 r0 = *reinterpret_cast<const uint2*>(&g_T[(size_t)s0 * DOUT + col]);
            uint2 r1 = *reinterpret_cast<const uint2*>(&g_T[(size_t)s1 * DOUT + col]);
            uint2 r2 = *reinterpret_cast<const uint2*>(&g_T[(size_t)s2 * DOUT + col]);
            uint2 r3 = *reinterpret_cast<const uint2*>(&g_T[(size_t)s3 * DOUT + col]);
#pragma unroll
            for (int q = 0; q < 4; q++) {
                uint2 r = (q == 0) ? r0 : (q == 1) ? r1 : (q == 2) ? r2 : r3;
                float2 a0 = __half22float2(*reinterpret_cast<__half2*>(&r.x));
                float2 a1 = __half22float2(*reinterpret_cast<__half2*>(&r.y));
                acc[0] += a0.x; acc[1] += a0.y; acc[2] += a1.x; acc[3] += a1.y;
            }
        } else {
            __half2 h0 = *reinterpret_cast<const __half2*>(&g_T[(size_t)s0 * DOUT + col]);
            __half2 h1 = *reinterpret_cast<const __half2*>(&g_T[(size_t)s1 * DOUT + col]);
            __half2 h2 = *reinterpret_cast<const __half2*>(&g_T[(size_t)s2 * DOUT + col]);
            __half2 h3 = *reinterpret_cast<const __half2*>(&g_T[(size_t)s3 * DOUT + col]);
            float2 a0 = __half22float2(h0), a1 = __half22float2(h1);
            float2 a2 = __half22float2(h2), a3 = __half22float2(h3);
            acc[0] += a0.x + a1.x + a2.x + a3.x;
            acc[1] += a0.y + a1.y + a2.y + a3.y;
        }
    }
    for (; p < end; p++) {
        int s0 = g_csr[p];
        if (F == 4) {
            uint2 r0 = *reinterpret_cast<const uint2*>(&g_T[(size_t)s0 * DOUT + col]);
            float2 a0 = __half22float2(*reinterpret_cast<__half2*>(&r0.x));
            float2 a1 = __half22float2(*reinterpret_cast<__half2*>(&r0.y));
            acc[0] += a0.x; acc[1] += a0.y; acc[2] += a1.x; acc[3] += a1.y;
        } else {
            __half2 h0 = *reinterpret_cast<const __half2*>(&g_T[(size_t)s0 * DOUT + col]);
            float2 a0 = __half22float2(h0);
            acc[0] += a0.x; acc[1] += a0.y;
        }
    }

    const float inv = g_inv[node];
    float o[F];
    float rv[F];
    {
        const __half* rrow = &g_R[(size_t)node * DOUT + col];
        if (F == 4) {
            uint2 r = *reinterpret_cast<const uint2*>(rrow);
            float2 a0 = __half22float2(*reinterpret_cast<__half2*>(&r.x));
            float2 a1 = __half22float2(*reinterpret_cast<__half2*>(&r.y));
            rv[0] = a0.x; rv[1] = a0.y; rv[2] = a1.x; rv[3] = a1.y;
        } else {
            float2 a0 = __half22float2(*reinterpret_cast<const __half2*>(rrow));
            rv[0] = a0.x; rv[1] = a0.y;
        }
    }
#pragma unroll
    for (int f = 0; f < F; f++)
        o[f] = acc[f] * inv + bl[col + f] + rv[f];

    if (DO_BN) {
#pragma unroll
        for (int f = 0; f < F; f++) {
            float gm = bng[col + f], bt = bnb[col + f];
            float mm = bnm[col + f], vv = bnv[col + f];
            o[f] = fmaxf((o[f] - mm) * (gm * rsqrtf(vv + 1e-5f)) + bt, 0.f);
        }
    }

    if (TO_OUT) {
        float* wptr = &out[(size_t)node * DOUT + col];
        if (F == 4)
            *reinterpret_cast<float4*>(wptr) = make_float4(o[0], o[1], o[2], o[3]);
        else
            *reinterpret_cast<float2*>(wptr) = make_float2(o[0], o[1]);
    } else {
        __half* wptr = &g_h[(size_t)node * DOUT + col];
        if (F == 4) {
            uint2 u;
            u.x = h2_to_u32(__floats2half2_rn(o[0], o[1]));
            u.y = h2_to_u32(__floats2half2_rn(o[2], o[3]));
            *reinterpret_cast<uint2*>(wptr) = u;
        } else {
            *reinterpret_cast<__half2*>(wptr) = __floats2half2_rn(o[0], o[1]);
        }
    }
}

// ---------------- launch ----------------
extern "C" void kernel_launch(void* const* d_in, const int* in_sizes, int n_in,
                              void* d_out, int out_size) {
    const float* x   = (const float*)d_in[0];
    const void*  ei  = d_in[1];
    const float* Wl0 = (const float*)d_in[2];
    const float* Wr0 = (const float*)d_in[3];
    const float* bl0 = (const float*)d_in[4];
    const float* Wl1 = (const float*)d_in[5];
    const float* Wr1 = (const float*)d_in[6];
    const float* bl1 = (const float*)d_in[7];
    const float* Wl2 = (const float*)d_in[8];
    const float* Wr2 = (const float*)d_in[9];
    const float* bl2 = (const float*)d_in[10];
    const float* g0 = (const float*)d_in[11];
    const float* b0 = (const float*)d_in[12];
    const float* m0 = (const float*)d_in[13];
    const float* v0 = (const float*)d_in[14];
    const float* g1 = (const float*)d_in[15];
    const float* b1 = (const float*)d_in[16];
    const float* m1 = (const float*)d_in[17];
    const float* v1 = (const float*)d_in[18];
    float* out = (float*)d_out;

    const int N = in_sizes[0] / 128;
    const int E = in_sizes[1] / 2;
    const int nb = (N + 1023) / 1024;

    // one-time side stream + fork/join events (host objects, no device memory)
    static cudaStream_t s_side = nullptr;
    static cudaEvent_t  s_fork = nullptr, s_join = nullptr;
    if (s_side == nullptr) {
        cudaStreamCreateWithFlags(&s_side, cudaStreamNonBlocking);
        cudaEventCreateWithFlags(&s_fork, cudaEventDisableTiming);
        cudaEventCreateWithFlags(&s_join, cudaEventDisableTiming);
    }

    // ---- fork: CSR build on side stream, weights+GEMM0 on main ----
    cudaEventRecord(s_fork, 0);
    cudaStreamWaitEvent(s_side, s_fork, 0);

    init_kernel<<<(N + 255) / 256, 256, 0, s_side>>>((const int*)ei, N);
    deg_kernel<<<(E + 255) / 256, 256, 0, s_side>>>(ei, E, N);
    scan_local_kernel<<<nb, 1024, 0, s_side>>>(N);
    scan_bsums_kernel<<<1, 128, 0, s_side>>>(nb, N);
    scan_add_kernel<<<nb, 1024, 0, s_side>>>(N);
    csr_fill_kernel<<<(E + 255) / 256, 256, 0, s_side>>>(ei, E, N);
    cudaEventRecord(s_join, s_side);

    dim3 gemmGridWide((N + 127) / 128, 2);
    dim3 gemmGridNarrow((N + 127) / 128, 1);
    int gatherBlocks = (N + 7) / 8;  // 8 warps per block

    concat_all_kernel<<<(81920 + 255) / 256, 256>>>(Wl0, Wr0, Wl1, Wr1, Wl2, Wr2);
    gemm_tc_kernel<256, false, 0><<<gemmGridWide, 256>>>(x, N);

    // ---- join: gather-0 needs CSR + GEMM0 ----
    cudaStreamWaitEvent(0, s_join, 0);
    gather_kernel<128, true, false><<<gatherBlocks, 256>>>(bl0, g0, b0, m0, v0, nullptr, N);

    // ---- layer 1: g_h -> g_h (BN + ReLU) ----
    gemm_tc_kernel<256, true, 1><<<gemmGridWide, 256>>>(nullptr, N);
    gather_kernel<128, true, false><<<gatherBlocks, 256>>>(bl1, g1, b1, m1, v1, nullptr, N);

    // ---- layer 2: g_h -> out (no BN/ReLU) ----
    gemm_tc_kernel<128, true, 2><<<gemmGridNarrow, 256>>>(nullptr, N);
    gather_kernel<64, false, true><<<gatherBlocks, 256>>>(bl2, nullptr, nullptr, nullptr, nullptr, out, N);
}